// round 7
// baseline (speedup 1.0000x reference)
#include <cuda_runtime.h>
#include <cstdint>
#include <math.h>

#define G_DIM   2304
#define HIDDEN  150
#define N_PAIRS 32768
#define N_MENT  4096
#define N_SEG   1024

#define TM 128
#define TN 160
#define SK 32                    // super-chunk K (one 128B line per row)
#define NSUP (G_DIM / SK)        // 72
#define KSPLIT 4
#define NSUP_PRE (NSUP / KSPLIT) // 18

#define APAD 36    // As row stride (words): conflict-free STS.128 + frag LDS
#define BPAD 168   // Bs row stride (words): 168 % 32 = 8 -> conflict-free

// ---------------- device scratch (static; no allocation) -------------------
__device__ float d_Wp[3 * G_DIM * TN];            // W1 tf32-rounded [sec][k][160]
__device__ float d_part[KSPLIT][2][N_MENT * TN];  // precompute partials
__device__ float d_Abuf[N_MENT * TN];
__device__ float d_Bbuf[N_MENT * TN];
__device__ float d_bias[3 * TN];
__device__ float d_scores[N_PAIRS];

__device__ __forceinline__ uint32_t f2tf32(float x) {
    uint32_t u;
    asm("cvt.rna.tf32.f32 %0, %1;" : "=r"(u) : "f"(x));
    return u;
}
__device__ __forceinline__ uint32_t smem_u32(const void* p) {
    uint32_t a;
    asm("{ .reg .u64 t; cvta.to.shared.u64 t, %1; cvt.u32.u64 %0, t; }"
        : "=r"(a) : "l"(p));
    return a;
}
__device__ __forceinline__ void cp_async16(uint32_t dst, const void* src) {
    asm volatile("cp.async.cg.shared.global [%0], [%1], 16;"
                 :: "r"(dst), "l"(src) : "memory");
}
#define CP_COMMIT() asm volatile("cp.async.commit_group;" ::: "memory")
#define CP_WAIT0()  asm volatile("cp.async.wait_group 0;" ::: "memory")

__device__ __forceinline__ void mma_tf32(float* d, const uint32_t* a,
                                         const uint32_t* b) {
    asm volatile(
        "mma.sync.aligned.m16n8k8.row.col.f32.tf32.tf32.f32 "
        "{%0,%1,%2,%3}, {%4,%5,%6,%7}, {%8,%9}, {%0,%1,%2,%3};"
        : "+f"(d[0]), "+f"(d[1]), "+f"(d[2]), "+f"(d[3])
        : "r"(a[0]), "r"(a[1]), "r"(a[2]), "r"(a[3]), "r"(b[0]), "r"(b[1]));
}

// ---------------------------------------------------------------------------
__global__ void prep_w_kernel(const float* __restrict__ W1) {
    int idx = blockIdx.x * 256 + threadIdx.x;
    if (idx >= 3 * G_DIM * TN) return;
    int sec = idx / (G_DIM * TN);
    int r = idx - sec * (G_DIM * TN);
    int k = r / TN, h = r - k * TN;
    float v = 0.f;
    if (h < HIDDEN)
        v = __uint_as_float(f2tf32(W1[(size_t)(sec * G_DIM + k) * HIDDEN + h]));
    d_Wp[idx] = v;
}

__global__ void bias_kernel(const float* __restrict__ spk,
                            const float* __restrict__ W1,
                            const float* __restrict__ b1) {
    const float* Wd = W1 + (size_t)(3 * G_DIM) * HIDDEN;
    for (int idx = threadIdx.x; idx < 3 * TN; idx += blockDim.x) {
        int s = idx / TN, h = idx % TN;
        float v = 0.f;
        if (h < HIDDEN) {
            v = b1[h];
            #pragma unroll
            for (int t = 0; t < 20; t++)
                v = fmaf(spk[s * 20 + t], Wd[(size_t)t * HIDDEN + h], v);
        }
        d_bias[idx] = v;
    }
}

// ---------------------------------------------------------------------------
// tf32 mma.sync GEMM, super-chunk SK=32 (one 128B line per A row per stage).
// 8 warps (2 M x 4 N), warp tile 64x40. A single-buffered (reg prefetch),
// B double-buffered per 16k half via cp.async. Every CP_WAIT0 is followed by
// __syncthreads() before any consumer reads the staged buffer.
// ---------------------------------------------------------------------------
template<bool PAIR>
__global__ __launch_bounds__(256, 2)
void mma_kernel(const float* __restrict__ G,
                const int*   __restrict__ m_ids,
                const int*   __restrict__ a_ids,
                const int*   __restrict__ spk_lbl,
                const float* __restrict__ mscores,
                const float* __restrict__ W2,
                const float* __restrict__ b2,
                int nsup) {
    __shared__ float As[TM][APAD];         // 18432 B
    __shared__ float Bs[2][16][BPAD];      // 21504 B
    __shared__ float srow[4][TM];
    __shared__ float bias_s[3 * TN];
    __shared__ float w2s[TN];

    const int tid = threadIdx.x;
    const int wid = tid >> 5, lane = tid & 31;
    const int gID = lane >> 2, tig = lane & 3;
    const int warp_m = wid & 1, warp_n = wid >> 1;
    const int base = blockIdx.x * TM;
    const int koff = PAIR ? 0 : blockIdx.z * NSUP_PRE * SK;

    if (PAIR) {
        if (tid < TN) w2s[tid] = (tid < HIDDEN) ? W2[tid] : 0.f;
        for (int i = tid; i < 3 * TN; i += 256) bias_s[i] = d_bias[i];
    }

    const float* Wp = d_Wp + (size_t)(PAIR ? 2 : blockIdx.y) * G_DIM * TN;

    // A staging: 8 threads per row, each thread one float4; 4 row-passes.
    const int rbase = tid >> 3;      // 0..31
    const int q = tid & 7;           // k-quad within SK
    size_t goff_i[4], goff_j[4];
    #pragma unroll
    for (int p = 0; p < 4; p++) {
        const int r = rbase + 32 * p;
        if (PAIR) {
            goff_i[p] = (size_t)m_ids[base + r] * G_DIM + koff + q * 4;
            goff_j[p] = (size_t)a_ids[base + r] * G_DIM + koff + q * 4;
        } else {
            goff_i[p] = (size_t)(base + r) * G_DIM + koff + q * 4;
        }
    }

    float acc[4][5][4];
    #pragma unroll
    for (int a = 0; a < 4; a++)
        #pragma unroll
        for (int b = 0; b < 5; b++)
            #pragma unroll
            for (int c = 0; c < 4; c++) acc[a][b][c] = 0.f;

    const uint32_t bs_base = smem_u32(Bs);
    const uint32_t* Au = reinterpret_cast<const uint32_t*>(As);
    const uint32_t* Bu = reinterpret_cast<const uint32_t*>(Bs);

    auto stage_B_half = [&](int S, int half) {
        const float* wsrc = Wp + (size_t)(koff + S * SK + half * 16) * TN;
        #pragma unroll
        for (int it = 0; it < 3; it++) {
            int u = tid + it * 256;
            if (u < 640) {
                int k = u / 40, hq = u - k * 40;
                cp_async16(bs_base + (uint32_t)((half * 16 + k) * BPAD + hq * 4) * 4u,
                           wsrc + k * TN + hq * 4);
            }
        }
    };
    auto load_A = [&](int S, float4* vi, float4* vj) {
        #pragma unroll
        for (int p = 0; p < 4; p++) {
            vi[p] = *reinterpret_cast<const float4*>(G + goff_i[p] + S * SK);
            if (PAIR)
                vj[p] = *reinterpret_cast<const float4*>(G + goff_j[p] + S * SK);
        }
    };
    auto make_prod = [&](const float4* vi, const float4* vj, float4* pr) {
        #pragma unroll
        for (int p = 0; p < 4; p++) {
            if (PAIR) {
                pr[p].x = __uint_as_float(f2tf32(vi[p].x * vj[p].x));
                pr[p].y = __uint_as_float(f2tf32(vi[p].y * vj[p].y));
                pr[p].z = __uint_as_float(f2tf32(vi[p].z * vj[p].z));
                pr[p].w = __uint_as_float(f2tf32(vi[p].w * vj[p].w));
            } else {
                pr[p].x = __uint_as_float(f2tf32(vi[p].x));
                pr[p].y = __uint_as_float(f2tf32(vi[p].y));
                pr[p].z = __uint_as_float(f2tf32(vi[p].z));
                pr[p].w = __uint_as_float(f2tf32(vi[p].w));
            }
        }
    };
    auto sts_prod = [&](const float4* pr) {
        #pragma unroll
        for (int p = 0; p < 4; p++)
            *reinterpret_cast<float4*>(&As[rbase + 32 * p][q * 4]) = pr[p];
    };
    auto mma_half = [&](int half) {
        #pragma unroll
        for (int ks = 0; ks < 2; ks++) {
            const int kg = half * 2 + ks;           // 0..3 within SK
            uint32_t af[4][4];
            #pragma unroll
            for (int tm = 0; tm < 4; tm++) {
                int m0 = warp_m * 64 + tm * 16 + gID;
                int b0 = m0 * APAD + kg * 8 + tig;
                af[tm][0] = Au[b0];
                af[tm][1] = Au[b0 + 8 * APAD];
                af[tm][2] = Au[b0 + 4];
                af[tm][3] = Au[b0 + 8 * APAD + 4];
            }
            #pragma unroll
            for (int tn = 0; tn < 5; tn++) {
                int col = warp_n * 40 + tn * 8 + gID;
                int r0 = half * (16 * BPAD) + (ks * 8 + tig) * BPAD + col;
                uint32_t bf[2];
                bf[0] = Bu[r0];
                bf[1] = Bu[r0 + 4 * BPAD];
                #pragma unroll
                for (int tm = 0; tm < 4; tm++)
                    mma_tf32(acc[tm][tn], af[tm], bf);
            }
        }
    };

    // ---- prologue: stage B(0,h0) and As(0); wait THEN sync ----
    {
        stage_B_half(0, 0);
        CP_COMMIT();
        float4 vi[4], vj[4], pr[4];
        load_A(0, vi, vj);
        make_prod(vi, vj, pr);
        sts_prod(pr);
        CP_WAIT0();
        __syncthreads();            // As(0) + B(0,h0) visible to all
    }

    for (int S = 0; S < nsup; S++) {
        const bool more = (S + 1 < nsup);
        stage_B_half(S, 1);                 // -> Bs[1]
        CP_COMMIT();
        float4 vi[4], vj[4], pr[4];
        if (more) load_A(S + 1, vi, vj);    // LDGs in flight over MMA h0
        mma_half(0);                        // reads Bs[0], As
        CP_WAIT0();                         // own B(S,h1) copies done
        __syncthreads();                    // B(S,h1) visible; Bs[0] free
        if (more) {
            stage_B_half(S + 1, 0);         // -> Bs[0]
            CP_COMMIT();
            make_prod(vi, vj, pr);
        }
        mma_half(1);                        // reads Bs[1], As
        __syncthreads();                    // all warps done with As
        if (more) sts_prod(pr);
        CP_WAIT0();                         // own B(S+1,h0) copies done
        __syncthreads();                    // As(S+1) + B(S+1,h0) visible
    }

    // ---- epilogue ----
    if (PAIR) {
        #pragma unroll
        for (int tm = 0; tm < 4; tm++) {
            #pragma unroll
            for (int rh = 0; rh < 2; rh++) {
                const int lr = warp_m * 64 + tm * 16 + rh * 8 + gID;
                const int p = base + lr;
                const int ii = m_ids[p], jj = a_ids[p], sp = spk_lbl[p];
                const float* Ar = d_Abuf + (size_t)ii * TN;
                const float* Br = d_Bbuf + (size_t)jj * TN;
                const float* bi = bias_s + sp * TN;
                float part = 0.f;
                #pragma unroll
                for (int tn = 0; tn < 5; tn++) {
                    const int h = warp_n * 40 + tn * 8 + tig * 2;
                    float2 av = *reinterpret_cast<const float2*>(Ar + h);
                    float2 bv = *reinterpret_cast<const float2*>(Br + h);
                    float v0 = acc[tm][tn][rh * 2 + 0] + av.x + bv.x + bi[h];
                    float v1 = acc[tm][tn][rh * 2 + 1] + av.y + bv.y + bi[h + 1];
                    part = fmaf(fmaxf(v0, 0.f), w2s[h], part);
                    part = fmaf(fmaxf(v1, 0.f), w2s[h + 1], part);
                }
                part += __shfl_xor_sync(0xffffffffu, part, 1);
                part += __shfl_xor_sync(0xffffffffu, part, 2);
                if (tig == 0) srow[warp_n][lr] = part;
            }
        }
        __syncthreads();
        if (tid < TM) {
            const int p = base + tid;
            d_scores[p] = srow[0][tid] + srow[1][tid] + srow[2][tid] + srow[3][tid]
                        + b2[0] + mscores[m_ids[p]] + mscores[a_ids[p]];
        }
    } else {
        float* out = &d_part[blockIdx.z][blockIdx.y][0];
        #pragma unroll
        for (int tm = 0; tm < 4; tm++) {
            #pragma unroll
            for (int rh = 0; rh < 2; rh++) {
                const int m = base + warp_m * 64 + tm * 16 + rh * 8 + gID;
                #pragma unroll
                for (int tn = 0; tn < 5; tn++) {
                    const int h = warp_n * 40 + tn * 8 + tig * 2;
                    float2 v = make_float2(acc[tm][tn][rh * 2 + 0],
                                           acc[tm][tn][rh * 2 + 1]);
                    *reinterpret_cast<float2*>(out + (size_t)m * TN + h) = v;
                }
            }
        }
    }
}

// ---------------------------------------------------------------------------
__global__ void combine_kernel() {
    const int TOT = 2 * N_MENT * TN / 4;   // float4 units per split
    int qk = blockIdx.x * 256 + threadIdx.x;
    if (qk >= TOT) return;
    const float4* p = reinterpret_cast<const float4*>(d_part);
    float4 a = p[qk], b = p[qk + TOT], c = p[qk + 2 * TOT], d = p[qk + 3 * TOT];
    float4 r;
    r.x = a.x + b.x + c.x + d.x;
    r.y = a.y + b.y + c.y + d.y;
    r.z = a.z + b.z + c.z + d.z;
    r.w = a.w + b.w + c.w + d.w;
    const int HALF = TOT / 2;
    if (qk < HALF) reinterpret_cast<float4*>(d_Abuf)[qk] = r;
    else           reinterpret_cast<float4*>(d_Bbuf)[qk - HALF] = r;
}

// ---------------------------------------------------------------------------
// Ragged softmax, one warp per segment (sorted segment_ids).
// ---------------------------------------------------------------------------
__global__ void softmax_kernel(const int* __restrict__ seg_ids,
                               float* __restrict__ out) {
    const int s = (blockIdx.x * blockDim.x + threadIdx.x) >> 5;
    const int lane = threadIdx.x & 31;
    if (s >= N_SEG) return;

    int lo = 0, hi = N_PAIRS;
    while (lo < hi) { int mid = (lo + hi) >> 1; if (seg_ids[mid] < s) lo = mid + 1; else hi = mid; }
    const int start = lo;
    hi = N_PAIRS;
    while (lo < hi) { int mid = (lo + hi) >> 1; if (seg_ids[mid] <= s) lo = mid + 1; else hi = mid; }
    const int end = lo;

    float m = 0.f;
    for (int p = start + lane; p < end; p += 32) m = fmaxf(m, d_scores[p]);
    #pragma unroll
    for (int o = 16; o; o >>= 1) m = fmaxf(m, __shfl_xor_sync(0xffffffffu, m, o));

    float sum = 0.f;
    for (int p = start + lane; p < end; p += 32) sum += expf(d_scores[p] - m);
    #pragma unroll
    for (int o = 16; o; o >>= 1) sum += __shfl_xor_sync(0xffffffffu, sum, o);

    const float eps_e = expf(-m);
    const float inv = 1.f / (sum + eps_e);
    for (int p = start + lane; p < end; p += 32)
        out[p] = expf(d_scores[p] - m) * inv;
    if (lane == 0) out[N_PAIRS + s] = eps_e * inv;
}

// ---------------------------------------------------------------------------
extern "C" void kernel_launch(void* const* d_in, const int* in_sizes, int n_in,
                              void* d_out, int out_size) {
    const float* g_i            = (const float*)d_in[0];
    const float* mention_scores = (const float*)d_in[1];
    const float* speaker_embed  = (const float*)d_in[2];
    const float* W1             = (const float*)d_in[3];
    const float* b1             = (const float*)d_in[4];
    const float* W2             = (const float*)d_in[5];
    const float* b2             = (const float*)d_in[6];
    const int*   mention_ids    = (const int*)d_in[7];
    const int*   antecedent_ids = (const int*)d_in[8];
    const int*   speaker_labels = (const int*)d_in[9];
    const int*   segment_ids    = (const int*)d_in[10];
    float* out = (float*)d_out;

    prep_w_kernel<<<(3 * G_DIM * TN + 255) / 256, 256>>>(W1);
    bias_kernel<<<1, 256>>>(speaker_embed, W1, b1);
    // precompute: 32 M-tiles x 2 sections x 4 K-splits = 256 CTAs (full wave)
    mma_kernel<false><<<dim3(N_MENT / TM, 2, KSPLIT), 256>>>(
        g_i, mention_ids, antecedent_ids, speaker_labels, mention_scores,
        W2, b2, NSUP_PRE);
    combine_kernel<<<(2 * N_MENT * TN / 4 + 255) / 256, 256>>>();
    // pair bilinear + fused epilogue: 256 CTAs
    mma_kernel<true><<<dim3(N_PAIRS / TM, 1, 1), 256>>>(
        g_i, mention_ids, antecedent_ids, speaker_labels, mention_scores,
        W2, b2, NSUP);
    softmax_kernel<<<(N_SEG * 32 + 255) / 256, 256>>>(segment_ids, out);
}

// round 8
// speedup vs baseline: 1.2963x; 1.2963x over previous
#include <cuda_runtime.h>
#include <cstdint>
#include <math.h>

#define G_DIM   2304
#define HIDDEN  150
#define N_PAIRS 32768
#define N_MENT  4096
#define N_SEG   1024

#define TM 128
#define TN 160
#define SK 32                    // K per stage (one 128B line per A row)
#define NSUP (G_DIM / SK)        // 72
#define KSPLIT 4
#define NSUP_PRE (NSUP / KSPLIT) // 18

#define APAD 36    // As row stride (words): frag LDS banks 4*gID+tig all distinct
#define BPAD 168   // Bs row stride (words): frag LDS banks 8*tig+gID all distinct

#define AS_WORDS (2 * TM * APAD)           // 9216
#define BS_WORDS (2 * SK * BPAD)           // 10752
#define DYN_BYTES ((AS_WORDS + BS_WORDS) * 4)   // 79872

// ---------------- device scratch (static; no allocation) -------------------
__device__ float d_Wp[3 * G_DIM * TN];            // W1 tf32-rounded [sec][k][160]
__device__ float d_part[KSPLIT][2][N_MENT * TN];  // precompute partials
__device__ float d_Abuf[N_MENT * TN];
__device__ float d_Bbuf[N_MENT * TN];
__device__ float d_bias[3 * TN];
__device__ float d_scores[N_PAIRS];

__device__ __forceinline__ uint32_t f2tf32(float x) {
    uint32_t u;
    asm("cvt.rna.tf32.f32 %0, %1;" : "=r"(u) : "f"(x));
    return u;
}
__device__ __forceinline__ uint32_t smem_u32(const void* p) {
    uint32_t a;
    asm("{ .reg .u64 t; cvta.to.shared.u64 t, %1; cvt.u32.u64 %0, t; }"
        : "=r"(a) : "l"(p));
    return a;
}
__device__ __forceinline__ void cp_async16(uint32_t dst, const void* src) {
    asm volatile("cp.async.cg.shared.global [%0], [%1], 16;"
                 :: "r"(dst), "l"(src) : "memory");
}
#define CP_COMMIT() asm volatile("cp.async.commit_group;" ::: "memory")
#define CP_WAIT0()  asm volatile("cp.async.wait_group 0;" ::: "memory")

__device__ __forceinline__ void mma_tf32(float* d, const uint32_t* a,
                                         const uint32_t* b) {
    asm volatile(
        "mma.sync.aligned.m16n8k8.row.col.f32.tf32.tf32.f32 "
        "{%0,%1,%2,%3}, {%4,%5,%6,%7}, {%8,%9}, {%0,%1,%2,%3};"
        : "+f"(d[0]), "+f"(d[1]), "+f"(d[2]), "+f"(d[3])
        : "r"(a[0]), "r"(a[1]), "r"(a[2]), "r"(a[3]), "r"(b[0]), "r"(b[1]));
}

// ---------------------------------------------------------------------------
__global__ void prep_w_kernel(const float* __restrict__ W1) {
    int idx = blockIdx.x * 256 + threadIdx.x;
    if (idx >= 3 * G_DIM * TN) return;
    int sec = idx / (G_DIM * TN);
    int r = idx - sec * (G_DIM * TN);
    int k = r / TN, h = r - k * TN;
    float v = 0.f;
    if (h < HIDDEN)
        v = __uint_as_float(f2tf32(W1[(size_t)(sec * G_DIM + k) * HIDDEN + h]));
    d_Wp[idx] = v;
}

__global__ void bias_kernel(const float* __restrict__ spk,
                            const float* __restrict__ W1,
                            const float* __restrict__ b1) {
    const float* Wd = W1 + (size_t)(3 * G_DIM) * HIDDEN;
    for (int idx = threadIdx.x; idx < 3 * TN; idx += blockDim.x) {
        int s = idx / TN, h = idx % TN;
        float v = 0.f;
        if (h < HIDDEN) {
            v = b1[h];
            #pragma unroll
            for (int t = 0; t < 20; t++)
                v = fmaf(spk[s * 20 + t], Wd[(size_t)t * HIDDEN + h], v);
        }
        d_bias[idx] = v;
    }
}

// ---------------------------------------------------------------------------
// tf32 mma.sync GEMM, SK=32 stages, A+B double-buffered in DYNAMIC smem,
// ONE __syncthreads per stage. 8 warps (2 M x 4 N), warp tile 64x40.
// A gathers: 8 threads/row, one float4/thread -> 4-line (minimum) wavefronts.
//   PAIR=false: partial g_i @ W1[sec] over K-split -> d_part[z][sec]
//   PAIR=true : (i∘j)@W1c full K + fused MLP epilogue -> d_scores
// ---------------------------------------------------------------------------
template<bool PAIR>
__global__ __launch_bounds__(256, 2)
void mma_kernel(const float* __restrict__ G,
                const int*   __restrict__ m_ids,
                const int*   __restrict__ a_ids,
                const int*   __restrict__ spk_lbl,
                const float* __restrict__ mscores,
                const float* __restrict__ W2,
                const float* __restrict__ b2,
                int nsup) {
    extern __shared__ float dyn[];
    float* Asm = dyn;                 // [2][TM][APAD]
    float* Bsm = dyn + AS_WORDS;      // [2][SK][BPAD]
    __shared__ float srow[4][TM];
    __shared__ float bias_s[3 * TN];
    __shared__ float w2s[TN];

    const int tid = threadIdx.x;
    const int wid = tid >> 5, lane = tid & 31;
    const int gID = lane >> 2, tig = lane & 3;
    const int warp_m = wid & 1, warp_n = wid >> 1;
    const int base = blockIdx.x * TM;
    const int koff = PAIR ? 0 : blockIdx.z * NSUP_PRE * SK;

    if (PAIR) {
        if (tid < TN) w2s[tid] = (tid < HIDDEN) ? W2[tid] : 0.f;
        for (int i = tid; i < 3 * TN; i += 256) bias_s[i] = d_bias[i];
    }

    const float* Wp = d_Wp + (size_t)(PAIR ? 2 : blockIdx.y) * G_DIM * TN;

    // A staging roles: 8 threads/row, q = float4 slot; 4 row passes.
    const int rbase = tid >> 3;   // 0..31
    const int q = tid & 7;        // 0..7
    int idx_i[4], idx_j[4];
    #pragma unroll
    for (int p = 0; p < 4; p++) {
        const int r = base + rbase + 32 * p;
        idx_i[p] = PAIR ? m_ids[r] : r;
        idx_j[p] = PAIR ? a_ids[r] : 0;
    }

    float acc[4][5][4];
    #pragma unroll
    for (int a = 0; a < 4; a++)
        #pragma unroll
        for (int b = 0; b < 5; b++)
            #pragma unroll
            for (int c = 0; c < 4; c++) acc[a][b][c] = 0.f;

    const uint32_t bs_base = smem_u32(Bsm);
    const uint32_t* Au = reinterpret_cast<const uint32_t*>(Asm);
    const uint32_t* Bu = reinterpret_cast<const uint32_t*>(Bsm);

    auto stage_B = [&](int S, int buf) {
        const float* wsrc = Wp + (size_t)(koff + S * SK) * TN;
        #pragma unroll
        for (int it = 0; it < 5; it++) {
            int u = tid + it * 256;            // 0..1279 float4 units
            int k = u / 40, hq = u - k * 40;
            cp_async16(bs_base + (uint32_t)((buf * SK + k) * BPAD + hq * 4) * 4u,
                       wsrc + k * TN + hq * 4);
        }
    };
    auto load2 = [&](int S, int p0, float4* vi, float4* vj) {
        #pragma unroll
        for (int t = 0; t < 2; t++) {
            const size_t off = koff + S * SK + q * 4;
            vi[t] = *reinterpret_cast<const float4*>(
                G + (size_t)idx_i[p0 + t] * G_DIM + off);
            if (PAIR)
                vj[t] = *reinterpret_cast<const float4*>(
                    G + (size_t)idx_j[p0 + t] * G_DIM + off);
        }
    };
    auto prod_sts = [&](int p0, const float4* vi, const float4* vj, int buf) {
        #pragma unroll
        for (int t = 0; t < 2; t++) {
            float4 pr;
            if (PAIR) {
                pr.x = __uint_as_float(f2tf32(vi[t].x * vj[t].x));
                pr.y = __uint_as_float(f2tf32(vi[t].y * vj[t].y));
                pr.z = __uint_as_float(f2tf32(vi[t].z * vj[t].z));
                pr.w = __uint_as_float(f2tf32(vi[t].w * vj[t].w));
            } else {
                pr.x = __uint_as_float(f2tf32(vi[t].x));
                pr.y = __uint_as_float(f2tf32(vi[t].y));
                pr.z = __uint_as_float(f2tf32(vi[t].z));
                pr.w = __uint_as_float(f2tf32(vi[t].w));
            }
            const int row = rbase + 32 * (p0 + t);
            *reinterpret_cast<float4*>(
                Asm + (size_t)(buf * TM + row) * APAD + q * 4) = pr;
        }
    };
    auto mma_ks = [&](int buf, int kg) {
        uint32_t af[4][4];
        #pragma unroll
        for (int tm = 0; tm < 4; tm++) {
            int m0 = warp_m * 64 + tm * 16 + gID;
            int b0 = (buf * TM + m0) * APAD + kg * 8 + tig;
            af[tm][0] = Au[b0];
            af[tm][1] = Au[b0 + 8 * APAD];
            af[tm][2] = Au[b0 + 4];
            af[tm][3] = Au[b0 + 8 * APAD + 4];
        }
        #pragma unroll
        for (int tn = 0; tn < 5; tn++) {
            int col = warp_n * 40 + tn * 8 + gID;
            int r0 = (buf * SK + kg * 8 + tig) * BPAD + col;
            uint32_t bf[2];
            bf[0] = Bu[r0];
            bf[1] = Bu[r0 + 4 * BPAD];
            #pragma unroll
            for (int tm = 0; tm < 4; tm++)
                mma_tf32(acc[tm][tn], af[tm], bf);
        }
    };

    // ---- prologue: stage S=0 into buffer 0 ----
    {
        stage_B(0, 0);
        CP_COMMIT();
        float4 vi[2], vj[2];
        load2(0, 0, vi, vj);  prod_sts(0, vi, vj, 0);
        load2(0, 2, vi, vj);  prod_sts(2, vi, vj, 0);
        CP_WAIT0();
        __syncthreads();
    }

    for (int S = 0; S < nsup; S++) {
        const int cur = S & 1, nxt = cur ^ 1;
        const bool more = (S + 1 < nsup);
        if (more) stage_B(S + 1, nxt);
        CP_COMMIT();
        float4 vi[2], vj[2];
        if (more) load2(S + 1, 0, vi, vj);   // LDGs fly over MMA ks 0-1
        mma_ks(cur, 0);
        mma_ks(cur, 1);
        if (more) {
            prod_sts(0, vi, vj, nxt);
            load2(S + 1, 2, vi, vj);         // LDGs fly over MMA ks 2-3
        }
        mma_ks(cur, 2);
        mma_ks(cur, 3);
        if (more) prod_sts(2, vi, vj, nxt);
        CP_WAIT0();
        __syncthreads();                     // single barrier per stage
    }

    // ---- epilogue ----
    if (PAIR) {
        #pragma unroll
        for (int tm = 0; tm < 4; tm++) {
            #pragma unroll
            for (int rh = 0; rh < 2; rh++) {
                const int lr = warp_m * 64 + tm * 16 + rh * 8 + gID;
                const int p = base + lr;
                const int ii = m_ids[p], jj = a_ids[p], sp = spk_lbl[p];
                const float* Ar = d_Abuf + (size_t)ii * TN;
                const float* Br = d_Bbuf + (size_t)jj * TN;
                const float* bi = bias_s + sp * TN;
                float part = 0.f;
                #pragma unroll
                for (int tn = 0; tn < 5; tn++) {
                    const int h = warp_n * 40 + tn * 8 + tig * 2;
                    float2 av = *reinterpret_cast<const float2*>(Ar + h);
                    float2 bv = *reinterpret_cast<const float2*>(Br + h);
                    float v0 = acc[tm][tn][rh * 2 + 0] + av.x + bv.x + bi[h];
                    float v1 = acc[tm][tn][rh * 2 + 1] + av.y + bv.y + bi[h + 1];
                    part = fmaf(fmaxf(v0, 0.f), w2s[h], part);
                    part = fmaf(fmaxf(v1, 0.f), w2s[h + 1], part);
                }
                part += __shfl_xor_sync(0xffffffffu, part, 1);
                part += __shfl_xor_sync(0xffffffffu, part, 2);
                if (tig == 0) srow[warp_n][lr] = part;
            }
        }
        __syncthreads();
        if (tid < TM) {
            const int p = base + tid;
            d_scores[p] = srow[0][tid] + srow[1][tid] + srow[2][tid] + srow[3][tid]
                        + b2[0] + mscores[m_ids[p]] + mscores[a_ids[p]];
        }
    } else {
        float* out = &d_part[blockIdx.z][blockIdx.y][0];
        #pragma unroll
        for (int tm = 0; tm < 4; tm++) {
            #pragma unroll
            for (int rh = 0; rh < 2; rh++) {
                const int m = base + warp_m * 64 + tm * 16 + rh * 8 + gID;
                #pragma unroll
                for (int tn = 0; tn < 5; tn++) {
                    const int h = warp_n * 40 + tn * 8 + tig * 2;
                    float2 v = make_float2(acc[tm][tn][rh * 2 + 0],
                                           acc[tm][tn][rh * 2 + 1]);
                    *reinterpret_cast<float2*>(out + (size_t)m * TN + h) = v;
                }
            }
        }
    }
}

// ---------------------------------------------------------------------------
__global__ void combine_kernel() {
    const int TOT = 2 * N_MENT * TN / 4;   // float4 units per split
    int qk = blockIdx.x * 256 + threadIdx.x;
    if (qk >= TOT) return;
    const float4* p = reinterpret_cast<const float4*>(d_part);
    float4 a = p[qk], b = p[qk + TOT], c = p[qk + 2 * TOT], d = p[qk + 3 * TOT];
    float4 r;
    r.x = a.x + b.x + c.x + d.x;
    r.y = a.y + b.y + c.y + d.y;
    r.z = a.z + b.z + c.z + d.z;
    r.w = a.w + b.w + c.w + d.w;
    const int HALF = TOT / 2;
    if (qk < HALF) reinterpret_cast<float4*>(d_Abuf)[qk] = r;
    else           reinterpret_cast<float4*>(d_Bbuf)[qk - HALF] = r;
}

// ---------------------------------------------------------------------------
__global__ void softmax_kernel(const int* __restrict__ seg_ids,
                               float* __restrict__ out) {
    const int s = (blockIdx.x * blockDim.x + threadIdx.x) >> 5;
    const int lane = threadIdx.x & 31;
    if (s >= N_SEG) return;

    int lo = 0, hi = N_PAIRS;
    while (lo < hi) { int mid = (lo + hi) >> 1; if (seg_ids[mid] < s) lo = mid + 1; else hi = mid; }
    const int start = lo;
    hi = N_PAIRS;
    while (lo < hi) { int mid = (lo + hi) >> 1; if (seg_ids[mid] <= s) lo = mid + 1; else hi = mid; }
    const int end = lo;

    float m = 0.f;
    for (int p = start + lane; p < end; p += 32) m = fmaxf(m, d_scores[p]);
    #pragma unroll
    for (int o = 16; o; o >>= 1) m = fmaxf(m, __shfl_xor_sync(0xffffffffu, m, o));

    float sum = 0.f;
    for (int p = start + lane; p < end; p += 32) sum += expf(d_scores[p] - m);
    #pragma unroll
    for (int o = 16; o; o >>= 1) sum += __shfl_xor_sync(0xffffffffu, sum, o);

    const float eps_e = expf(-m);
    const float inv = 1.f / (sum + eps_e);
    for (int p = start + lane; p < end; p += 32)
        out[p] = expf(d_scores[p] - m) * inv;
    if (lane == 0) out[N_PAIRS + s] = eps_e * inv;
}

// ---------------------------------------------------------------------------
extern "C" void kernel_launch(void* const* d_in, const int* in_sizes, int n_in,
                              void* d_out, int out_size) {
    const float* g_i            = (const float*)d_in[0];
    const float* mention_scores = (const float*)d_in[1];
    const float* speaker_embed  = (const float*)d_in[2];
    const float* W1             = (const float*)d_in[3];
    const float* b1             = (const float*)d_in[4];
    const float* W2             = (const float*)d_in[5];
    const float* b2             = (const float*)d_in[6];
    const int*   mention_ids    = (const int*)d_in[7];
    const int*   antecedent_ids = (const int*)d_in[8];
    const int*   speaker_labels = (const int*)d_in[9];
    const int*   segment_ids    = (const int*)d_in[10];
    float* out = (float*)d_out;

    // allow >48KB dynamic smem (idempotent; not an allocation)
    cudaFuncSetAttribute(mma_kernel<false>,
                         cudaFuncAttributeMaxDynamicSharedMemorySize, DYN_BYTES);
    cudaFuncSetAttribute(mma_kernel<true>,
                         cudaFuncAttributeMaxDynamicSharedMemorySize, DYN_BYTES);

    prep_w_kernel<<<(3 * G_DIM * TN + 255) / 256, 256>>>(W1);
    bias_kernel<<<1, 256>>>(speaker_embed, W1, b1);
    // precompute: 32 M-tiles x 2 sections x 4 K-splits = 256 CTAs (full wave)
    mma_kernel<false><<<dim3(N_MENT / TM, 2, KSPLIT), 256, DYN_BYTES>>>(
        g_i, mention_ids, antecedent_ids, speaker_labels, mention_scores,
        W2, b2, NSUP_PRE);
    combine_kernel<<<(2 * N_MENT * TN / 4 + 255) / 256, 256>>>();
    // pair bilinear + fused epilogue: 256 CTAs
    mma_kernel<true><<<dim3(N_PAIRS / TM, 1, 1), 256, DYN_BYTES>>>(
        g_i, mention_ids, antecedent_ids, speaker_labels, mention_scores,
        W2, b2, NSUP);
    softmax_kernel<<<(N_SEG * 32 + 255) / 256, 256>>>(segment_ids, out);
}

// round 9
// speedup vs baseline: 2.1185x; 1.6343x over previous
#include <cuda_runtime.h>
#include <cuda_fp16.h>
#include <cstdint>
#include <math.h>

#define G_DIM   2304
#define HIDDEN  150
#define N_PAIRS 32768
#define N_MENT  4096
#define N_SEG   1024

#define TM 128
#define TN 160
#define SK 32                    // K per stage
#define NSUP (G_DIM / SK)        // 72
#define KSPLIT 4
#define NSUP_PRE (NSUP / KSPLIT) // 18

#define RPAD 20    // uint row stride (16 data uints + 4 pad): banks 20g+t distinct

#define AS_UINTS (2 * TM * RPAD)           // 5120
#define BS_UINTS (2 * TN * RPAD)           // 6400
#define DYN_BYTES ((AS_UINTS + BS_UINTS) * 4)   // 46080

// ---------------- device scratch (static; no allocation) -------------------
__device__ __half d_Wh[3 * TN * G_DIM];           // W1^T fp16 [sec][h][k]
__device__ float d_part[KSPLIT][2][N_MENT * TN];  // precompute partials
__device__ float d_Abuf[N_MENT * TN];
__device__ float d_Bbuf[N_MENT * TN];
__device__ float d_bias[3 * TN];
__device__ float d_scores[N_PAIRS];

__device__ __forceinline__ uint32_t smem_u32(const void* p) {
    uint32_t a;
    asm("{ .reg .u64 t; cvta.to.shared.u64 t, %1; cvt.u32.u64 %0, t; }"
        : "=r"(a) : "l"(p));
    return a;
}
__device__ __forceinline__ void cp_async16(uint32_t dst, const void* src) {
    asm volatile("cp.async.cg.shared.global [%0], [%1], 16;"
                 :: "r"(dst), "l"(src) : "memory");
}
#define CP_COMMIT() asm volatile("cp.async.commit_group;" ::: "memory")
#define CP_WAIT0()  asm volatile("cp.async.wait_group 0;" ::: "memory")

__device__ __forceinline__ void mma_f16(float* d, const uint32_t* a,
                                        const uint32_t* b) {
    asm volatile(
        "mma.sync.aligned.m16n8k16.row.col.f32.f16.f16.f32 "
        "{%0,%1,%2,%3}, {%4,%5,%6,%7}, {%8,%9}, {%0,%1,%2,%3};"
        : "+f"(d[0]), "+f"(d[1]), "+f"(d[2]), "+f"(d[3])
        : "r"(a[0]), "r"(a[1]), "r"(a[2]), "r"(a[3]), "r"(b[0]), "r"(b[1]));
}

// ---------------------------------------------------------------------------
// Transpose W1 sections to fp16 [sec][h][k]; rows h>=150 zeroed.
// ---------------------------------------------------------------------------
__global__ void prep_w_kernel(const float* __restrict__ W1) {
    __shared__ float t[32][33];
    const int k0 = blockIdx.x * 32, h0 = blockIdx.y * 32, sec = blockIdx.z;
    const int tx = threadIdx.x, ty = threadIdx.y;
    #pragma unroll
    for (int r = 0; r < 4; r++) {
        int ky = ty + r * 8, h = h0 + tx;
        t[ky][tx] = (h < HIDDEN)
            ? W1[(size_t)(sec * G_DIM + k0 + ky) * HIDDEN + h] : 0.f;
    }
    __syncthreads();
    #pragma unroll
    for (int r = 0; r < 4; r++) {
        int hy = ty + r * 8;
        d_Wh[(size_t)sec * TN * G_DIM + (size_t)(h0 + hy) * G_DIM + k0 + tx] =
            __float2half_rn(t[tx][hy]);
    }
}

// ---------------------------------------------------------------------------
__global__ void bias_kernel(const float* __restrict__ spk,
                            const float* __restrict__ W1,
                            const float* __restrict__ b1) {
    const float* Wd = W1 + (size_t)(3 * G_DIM) * HIDDEN;
    for (int idx = threadIdx.x; idx < 3 * TN; idx += blockDim.x) {
        int s = idx / TN, h = idx % TN;
        float v = 0.f;
        if (h < HIDDEN) {
            v = b1[h];
            #pragma unroll
            for (int t = 0; t < 20; t++)
                v = fmaf(spk[s * 20 + t], Wd[(size_t)t * HIDDEN + h], v);
        }
        d_bias[idx] = v;
    }
}

// ---------------------------------------------------------------------------
// fp16 mma.sync GEMM (m16n8k16), SK=32 stages, A+B double-buffered in dynamic
// smem, ONE __syncthreads per stage. 8 warps (2 M x 4 N), warp tile 64x40.
//   PAIR=false: partial g_i @ W1[sec] over K-split -> d_part[z][sec]
//   PAIR=true : (i∘j)@W1c full K + fused MLP epilogue -> d_scores
// Layouts (uint granularity, RPAD=20):
//   A: [buf][row0..127][16 uints = 32 halfs k]   frag: (row, ks*8+tig, +4)
//   B: [buf][col0..159][16 uints = 32 halfs k]   frag: (col, ks*8+tig, +4)
// ---------------------------------------------------------------------------
template<bool PAIR>
__global__ __launch_bounds__(256, 2)
void mma_kernel(const float* __restrict__ G,
                const int*   __restrict__ m_ids,
                const int*   __restrict__ a_ids,
                const int*   __restrict__ spk_lbl,
                const float* __restrict__ mscores,
                const float* __restrict__ W2,
                const float* __restrict__ b2,
                int nsup) {
    extern __shared__ uint32_t dynu[];
    uint32_t* Au = dynu;                 // [2][TM][RPAD]
    uint32_t* Bu = dynu + AS_UINTS;      // [2][TN][RPAD]
    __shared__ float srow[4][TM];
    __shared__ float bias_s[3 * TN];
    __shared__ float w2s[TN];

    const int tid = threadIdx.x;
    const int wid = tid >> 5, lane = tid & 31;
    const int gID = lane >> 2, tig = lane & 3;
    const int warp_m = wid & 1, warp_n = wid >> 1;
    const int base = blockIdx.x * TM;
    const int koff = PAIR ? 0 : blockIdx.z * NSUP_PRE * SK;

    if (PAIR) {
        if (tid < TN) w2s[tid] = (tid < HIDDEN) ? W2[tid] : 0.f;
        for (int i = tid; i < 3 * TN; i += 256) bias_s[i] = d_bias[i];
    }

    const __half* Wh = d_Wh + (size_t)(PAIR ? 2 : blockIdx.y) * TN * G_DIM;

    // A staging roles: 8 threads/row, q = k-quad (4 floats -> 2 uints of half2)
    const int rbase = tid >> 3;   // 0..31
    const int q = tid & 7;        // 0..7
    int idx_i[4], idx_j[4];
    #pragma unroll
    for (int p = 0; p < 4; p++) {
        const int r = base + rbase + 32 * p;
        idx_i[p] = PAIR ? m_ids[r] : r;
        idx_j[p] = PAIR ? a_ids[r] : 0;
    }

    float acc[4][5][4];
    #pragma unroll
    for (int a = 0; a < 4; a++)
        #pragma unroll
        for (int b = 0; b < 5; b++)
            #pragma unroll
            for (int c = 0; c < 4; c++) acc[a][b][c] = 0.f;

    const uint32_t bs_base = smem_u32(Bu);

    auto stage_B = [&](int S, int buf) {
        // 160 cols x 64B (4 x cp16) = 640 units; 256 threads
        #pragma unroll
        for (int it = 0; it < 3; it++) {
            int u = tid + it * 256;
            if (u < 640) {
                int col = u >> 2, q4 = u & 3;
                const __half* src = Wh + (size_t)col * G_DIM + koff + S * SK + q4 * 8;
                cp_async16(bs_base + (uint32_t)((buf * TN + col) * RPAD + q4 * 4) * 4u,
                           src);
            }
        }
    };
    auto load2 = [&](int S, int p0, float4* vi, float4* vj) {
        #pragma unroll
        for (int t = 0; t < 2; t++) {
            const size_t off = koff + S * SK + q * 4;
            vi[t] = *reinterpret_cast<const float4*>(
                G + (size_t)idx_i[p0 + t] * G_DIM + off);
            if (PAIR)
                vj[t] = *reinterpret_cast<const float4*>(
                    G + (size_t)idx_j[p0 + t] * G_DIM + off);
        }
    };
    auto prod_sts = [&](int p0, const float4* vi, const float4* vj, int buf) {
        #pragma unroll
        for (int t = 0; t < 2; t++) {
            __half2 h0, h1;
            if (PAIR) {
                h0 = __floats2half2_rn(vi[t].x * vj[t].x, vi[t].y * vj[t].y);
                h1 = __floats2half2_rn(vi[t].z * vj[t].z, vi[t].w * vj[t].w);
            } else {
                h0 = __floats2half2_rn(vi[t].x, vi[t].y);
                h1 = __floats2half2_rn(vi[t].z, vi[t].w);
            }
            const int row = rbase + 32 * (p0 + t);
            uint2 u;
            u.x = *reinterpret_cast<uint32_t*>(&h0);
            u.y = *reinterpret_cast<uint32_t*>(&h1);
            *reinterpret_cast<uint2*>(Au + (size_t)(buf * TM + row) * RPAD + q * 2) = u;
        }
    };
    auto mma_ks = [&](int buf, int ks) {
        uint32_t af[4][4];
        #pragma unroll
        for (int tm = 0; tm < 4; tm++) {
            int m0 = warp_m * 64 + tm * 16 + gID;
            int b0 = (buf * TM + m0) * RPAD + ks * 8 + tig;
            af[tm][0] = Au[b0];
            af[tm][1] = Au[b0 + 8 * RPAD];
            af[tm][2] = Au[b0 + 4];
            af[tm][3] = Au[b0 + 8 * RPAD + 4];
        }
        #pragma unroll
        for (int tn = 0; tn < 5; tn++) {
            int col = warp_n * 40 + tn * 8 + gID;
            int r0 = (buf * TN + col) * RPAD + ks * 8 + tig;
            uint32_t bf[2];
            bf[0] = Bu[r0];
            bf[1] = Bu[r0 + 4];
            #pragma unroll
            for (int tm = 0; tm < 4; tm++)
                mma_f16(acc[tm][tn], af[tm], bf);
        }
    };

    // ---- prologue: stage S=0 into buffer 0 ----
    {
        stage_B(0, 0);
        CP_COMMIT();
        float4 vi[2], vj[2];
        load2(0, 0, vi, vj);  prod_sts(0, vi, vj, 0);
        load2(0, 2, vi, vj);  prod_sts(2, vi, vj, 0);
        CP_WAIT0();
        __syncthreads();
    }

    for (int S = 0; S < nsup; S++) {
        const int cur = S & 1, nxt = cur ^ 1;
        const bool more = (S + 1 < nsup);
        if (more) stage_B(S + 1, nxt);
        CP_COMMIT();
        float4 vi[2], vj[2];
        if (more) load2(S + 1, 0, vi, vj);   // LDGs fly over MMA ks=0
        mma_ks(cur, 0);
        if (more) {
            prod_sts(0, vi, vj, nxt);
            load2(S + 1, 2, vi, vj);         // LDGs fly over MMA ks=1
        }
        mma_ks(cur, 1);
        if (more) prod_sts(2, vi, vj, nxt);
        CP_WAIT0();
        __syncthreads();                     // single barrier per stage
    }

    // ---- epilogue ----
    if (PAIR) {
        #pragma unroll
        for (int tm = 0; tm < 4; tm++) {
            #pragma unroll
            for (int rh = 0; rh < 2; rh++) {
                const int lr = warp_m * 64 + tm * 16 + rh * 8 + gID;
                const int p = base + lr;
                const int ii = m_ids[p], jj = a_ids[p], sp = spk_lbl[p];
                const float* Ar = d_Abuf + (size_t)ii * TN;
                const float* Br = d_Bbuf + (size_t)jj * TN;
                const float* bi = bias_s + sp * TN;
                float part = 0.f;
                #pragma unroll
                for (int tn = 0; tn < 5; tn++) {
                    const int h = warp_n * 40 + tn * 8 + tig * 2;
                    float2 av = *reinterpret_cast<const float2*>(Ar + h);
                    float2 bv = *reinterpret_cast<const float2*>(Br + h);
                    float v0 = acc[tm][tn][rh * 2 + 0] + av.x + bv.x + bi[h];
                    float v1 = acc[tm][tn][rh * 2 + 1] + av.y + bv.y + bi[h + 1];
                    part = fmaf(fmaxf(v0, 0.f), w2s[h], part);
                    part = fmaf(fmaxf(v1, 0.f), w2s[h + 1], part);
                }
                part += __shfl_xor_sync(0xffffffffu, part, 1);
                part += __shfl_xor_sync(0xffffffffu, part, 2);
                if (tig == 0) srow[warp_n][lr] = part;
            }
        }
        __syncthreads();
        if (tid < TM) {
            const int p = base + tid;
            d_scores[p] = srow[0][tid] + srow[1][tid] + srow[2][tid] + srow[3][tid]
                        + b2[0] + mscores[m_ids[p]] + mscores[a_ids[p]];
        }
    } else {
        float* out = &d_part[blockIdx.z][blockIdx.y][0];
        #pragma unroll
        for (int tm = 0; tm < 4; tm++) {
            #pragma unroll
            for (int rh = 0; rh < 2; rh++) {
                const int m = base + warp_m * 64 + tm * 16 + rh * 8 + gID;
                #pragma unroll
                for (int tn = 0; tn < 5; tn++) {
                    const int h = warp_n * 40 + tn * 8 + tig * 2;
                    float2 v = make_float2(acc[tm][tn][rh * 2 + 0],
                                           acc[tm][tn][rh * 2 + 1]);
                    *reinterpret_cast<float2*>(out + (size_t)m * TN + h) = v;
                }
            }
        }
    }
}

// ---------------------------------------------------------------------------
__global__ void combine_kernel() {
    const int TOT = 2 * N_MENT * TN / 4;   // float4 units per split
    int qk = blockIdx.x * 256 + threadIdx.x;
    if (qk >= TOT) return;
    const float4* p = reinterpret_cast<const float4*>(d_part);
    float4 a = p[qk], b = p[qk + TOT], c = p[qk + 2 * TOT], d = p[qk + 3 * TOT];
    float4 r;
    r.x = a.x + b.x + c.x + d.x;
    r.y = a.y + b.y + c.y + d.y;
    r.z = a.z + b.z + c.z + d.z;
    r.w = a.w + b.w + c.w + d.w;
    const int HALF = TOT / 2;
    if (qk < HALF) reinterpret_cast<float4*>(d_Abuf)[qk] = r;
    else           reinterpret_cast<float4*>(d_Bbuf)[qk - HALF] = r;
}

// ---------------------------------------------------------------------------
__global__ void softmax_kernel(const int* __restrict__ seg_ids,
                               float* __restrict__ out) {
    const int s = (blockIdx.x * blockDim.x + threadIdx.x) >> 5;
    const int lane = threadIdx.x & 31;
    if (s >= N_SEG) return;

    int lo = 0, hi = N_PAIRS;
    while (lo < hi) { int mid = (lo + hi) >> 1; if (seg_ids[mid] < s) lo = mid + 1; else hi = mid; }
    const int start = lo;
    hi = N_PAIRS;
    while (lo < hi) { int mid = (lo + hi) >> 1; if (seg_ids[mid] <= s) lo = mid + 1; else hi = mid; }
    const int end = lo;

    float m = 0.f;
    for (int p = start + lane; p < end; p += 32) m = fmaxf(m, d_scores[p]);
    #pragma unroll
    for (int o = 16; o; o >>= 1) m = fmaxf(m, __shfl_xor_sync(0xffffffffu, m, o));

    float sum = 0.f;
    for (int p = start + lane; p < end; p += 32) sum += expf(d_scores[p] - m);
    #pragma unroll
    for (int o = 16; o; o >>= 1) sum += __shfl_xor_sync(0xffffffffu, sum, o);

    const float eps_e = expf(-m);
    const float inv = 1.f / (sum + eps_e);
    for (int p = start + lane; p < end; p += 32)
        out[p] = expf(d_scores[p] - m) * inv;
    if (lane == 0) out[N_PAIRS + s] = eps_e * inv;
}

// ---------------------------------------------------------------------------
extern "C" void kernel_launch(void* const* d_in, const int* in_sizes, int n_in,
                              void* d_out, int out_size) {
    const float* g_i            = (const float*)d_in[0];
    const float* mention_scores = (const float*)d_in[1];
    const float* speaker_embed  = (const float*)d_in[2];
    const float* W1             = (const float*)d_in[3];
    const float* b1             = (const float*)d_in[4];
    const float* W2             = (const float*)d_in[5];
    const float* b2             = (const float*)d_in[6];
    const int*   mention_ids    = (const int*)d_in[7];
    const int*   antecedent_ids = (const int*)d_in[8];
    const int*   speaker_labels = (const int*)d_in[9];
    const int*   segment_ids    = (const int*)d_in[10];
    float* out = (float*)d_out;

    // static smem (4.6KB) + dynamic (45KB) > 48KB default -> opt in
    cudaFuncSetAttribute(mma_kernel<false>,
                         cudaFuncAttributeMaxDynamicSharedMemorySize, DYN_BYTES);
    cudaFuncSetAttribute(mma_kernel<true>,
                         cudaFuncAttributeMaxDynamicSharedMemorySize, DYN_BYTES);

    prep_w_kernel<<<dim3(G_DIM / 32, TN / 32, 3), dim3(32, 8)>>>(W1);
    bias_kernel<<<1, 256>>>(speaker_embed, W1, b1);
    // precompute: 32 M-tiles x 2 sections x 4 K-splits = 256 CTAs (full wave)
    mma_kernel<false><<<dim3(N_MENT / TM, 2, KSPLIT), 256, DYN_BYTES>>>(
        g_i, mention_ids, antecedent_ids, speaker_labels, mention_scores,
        W2, b2, NSUP_PRE);
    combine_kernel<<<(2 * N_MENT * TN / 4 + 255) / 256, 256>>>();
    // pair bilinear + fused epilogue: 256 CTAs
    mma_kernel<true><<<dim3(N_PAIRS / TM, 1, 1), 256, DYN_BYTES>>>(
        g_i, mention_ids, antecedent_ids, speaker_labels, mention_scores,
        W2, b2, NSUP);
    softmax_kernel<<<(N_SEG * 32 + 255) / 256, 256>>>(segment_ids, out);
}

// round 10
// speedup vs baseline: 2.2370x; 1.0559x over previous
#include <cuda_runtime.h>
#include <cuda_fp16.h>
#include <cstdint>
#include <math.h>

#define G_DIM   2304
#define HIDDEN  150
#define N_PAIRS 32768
#define N_MENT  4096
#define N_SEG   1024

#define TM 128
#define TN 160
#define SK 32                    // K per stage
#define NSUP (G_DIM / SK)        // 72
#define KSPLIT 4
#define NSUP_PRE (NSUP / KSPLIT) // 18

#define RPAD 20    // uint row stride: ldmatrix phases hit all 32 banks

#define AS_UINTS (2 * TM * RPAD)           // 5120
#define BS_UINTS (2 * TN * RPAD)           // 6400
#define DYN_BYTES ((AS_UINTS + BS_UINTS) * 4)   // 46080

// ---------------- device scratch (static; no allocation) -------------------
__device__ __half d_Wh[3 * TN * G_DIM];           // W1^T fp16 [sec][h][k]
__device__ float d_part[KSPLIT][2][N_MENT * TN];  // precompute partials
__device__ float d_Abuf[N_MENT * TN];
__device__ float d_Bbuf[N_MENT * TN];
__device__ float d_bias[3 * TN];
__device__ float d_scores[N_PAIRS];

__device__ __forceinline__ uint32_t smem_u32(const void* p) {
    uint32_t a;
    asm("{ .reg .u64 t; cvta.to.shared.u64 t, %1; cvt.u32.u64 %0, t; }"
        : "=r"(a) : "l"(p));
    return a;
}
__device__ __forceinline__ void cp_async16(uint32_t dst, const void* src) {
    asm volatile("cp.async.cg.shared.global [%0], [%1], 16;"
                 :: "r"(dst), "l"(src) : "memory");
}
#define CP_COMMIT() asm volatile("cp.async.commit_group;" ::: "memory")
#define CP_WAIT0()  asm volatile("cp.async.wait_group 0;" ::: "memory")

__device__ __forceinline__ void mma_f16(float* d, const uint32_t* a,
                                        const uint32_t* b) {
    asm volatile(
        "mma.sync.aligned.m16n8k16.row.col.f32.f16.f16.f32 "
        "{%0,%1,%2,%3}, {%4,%5,%6,%7}, {%8,%9}, {%0,%1,%2,%3};"
        : "+f"(d[0]), "+f"(d[1]), "+f"(d[2]), "+f"(d[3])
        : "r"(a[0]), "r"(a[1]), "r"(a[2]), "r"(a[3]), "r"(b[0]), "r"(b[1]));
}
__device__ __forceinline__ void ldmatrix_x4(uint32_t* r, uint32_t addr) {
    asm volatile("ldmatrix.sync.aligned.m8n8.x4.shared.b16 {%0,%1,%2,%3}, [%4];"
                 : "=r"(r[0]), "=r"(r[1]), "=r"(r[2]), "=r"(r[3]) : "r"(addr));
}
__device__ __forceinline__ void ldmatrix_x2(uint32_t* r, uint32_t addr) {
    asm volatile("ldmatrix.sync.aligned.m8n8.x2.shared.b16 {%0,%1}, [%2];"
                 : "=r"(r[0]), "=r"(r[1]) : "r"(addr));
}

// ---------------------------------------------------------------------------
// Transpose W1 sections to fp16 [sec][h][k]; rows h>=150 zeroed.
// ---------------------------------------------------------------------------
__global__ void prep_w_kernel(const float* __restrict__ W1) {
    __shared__ float t[32][33];
    const int k0 = blockIdx.x * 32, h0 = blockIdx.y * 32, sec = blockIdx.z;
    const int tx = threadIdx.x, ty = threadIdx.y;
    #pragma unroll
    for (int r = 0; r < 4; r++) {
        int ky = ty + r * 8, h = h0 + tx;
        t[ky][tx] = (h < HIDDEN)
            ? W1[(size_t)(sec * G_DIM + k0 + ky) * HIDDEN + h] : 0.f;
    }
    __syncthreads();
    #pragma unroll
    for (int r = 0; r < 4; r++) {
        int hy = ty + r * 8;
        d_Wh[(size_t)sec * TN * G_DIM + (size_t)(h0 + hy) * G_DIM + k0 + tx] =
            __float2half_rn(t[tx][hy]);
    }
}

// ---------------------------------------------------------------------------
__global__ void bias_kernel(const float* __restrict__ spk,
                            const float* __restrict__ W1,
                            const float* __restrict__ b1) {
    const float* Wd = W1 + (size_t)(3 * G_DIM) * HIDDEN;
    for (int idx = threadIdx.x; idx < 3 * TN; idx += blockDim.x) {
        int s = idx / TN, h = idx % TN;
        float v = 0.f;
        if (h < HIDDEN) {
            v = b1[h];
            #pragma unroll
            for (int t = 0; t < 20; t++)
                v = fmaf(spk[s * 20 + t], Wd[(size_t)t * HIDDEN + h], v);
        }
        d_bias[idx] = v;
    }
}

// ---------------------------------------------------------------------------
// fp16 mma.sync GEMM (m16n8k16) with ldmatrix fragment loads.
// SK=32 stages, A+B double-buffered in dynamic smem, ONE barrier per stage.
// 8 warps (2 M x 4 N), warp tile 64x40.
//   PAIR=false: partial g_i @ W1[sec] over K-split -> d_part[z][sec]
//   PAIR=true : (i∘j)@W1c full K + fused MLP epilogue -> d_scores
// ---------------------------------------------------------------------------
template<bool PAIR>
__global__ __launch_bounds__(256, 2)
void mma_kernel(const float* __restrict__ G,
                const int*   __restrict__ m_ids,
                const int*   __restrict__ a_ids,
                const int*   __restrict__ spk_lbl,
                const float* __restrict__ mscores,
                const float* __restrict__ W2,
                const float* __restrict__ b2,
                int nsup) {
    extern __shared__ uint32_t dynu[];
    uint32_t* Au = dynu;                 // [2][TM][RPAD]
    uint32_t* Bu = dynu + AS_UINTS;      // [2][TN][RPAD]
    __shared__ float srow[4][TM];
    __shared__ float bias_s[3 * TN];
    __shared__ float w2s[TN];

    const int tid = threadIdx.x;
    const int wid = tid >> 5, lane = tid & 31;
    const int gID = lane >> 2, tig = lane & 3;
    const int warp_m = wid & 1, warp_n = wid >> 1;
    const int base = blockIdx.x * TM;
    const int koff = PAIR ? 0 : blockIdx.z * NSUP_PRE * SK;

    if (PAIR) {
        if (tid < TN) w2s[tid] = (tid < HIDDEN) ? W2[tid] : 0.f;
        for (int i = tid; i < 3 * TN; i += 256) bias_s[i] = d_bias[i];
    }

    const __half* Wh = d_Wh + (size_t)(PAIR ? 2 : blockIdx.y) * TN * G_DIM;

    // A staging roles: 8 threads/row, q = k-quad
    const int rbase = tid >> 3;   // 0..31
    const int q = tid & 7;        // 0..7
    int idx_i[4], idx_j[4];
    #pragma unroll
    for (int p = 0; p < 4; p++) {
        const int r = base + rbase + 32 * p;
        idx_i[p] = PAIR ? m_ids[r] : r;
        idx_j[p] = PAIR ? a_ids[r] : 0;
    }

    float acc[4][5][4];
    #pragma unroll
    for (int a = 0; a < 4; a++)
        #pragma unroll
        for (int b = 0; b < 5; b++)
            #pragma unroll
            for (int c = 0; c < 4; c++) acc[a][b][c] = 0.f;

    const uint32_t au_base = smem_u32(Au);
    const uint32_t bs_base = smem_u32(Bu);

    // ldmatrix lane-address components (bytes)
    const int a_rowsel = (lane & 7) + ((lane >> 3) & 1) * 8;   // 0..15
    const int a_ksel   = (lane >> 4) & 1;                       // k half (x4)
    const uint32_t a_lane_off = au_base
        + 4u * ((uint32_t)a_rowsel * RPAD + (uint32_t)a_ksel * 4);
    const int b_colsel = lane & 7;
    const int b_ksel   = (lane >> 3) & 1;                       // k half (x2)
    const uint32_t b_lane_off = bs_base
        + 4u * ((uint32_t)b_colsel * RPAD + (uint32_t)b_ksel * 4);

    auto stage_B = [&](int S, int buf) {
        #pragma unroll
        for (int it = 0; it < 3; it++) {
            int u = tid + it * 256;
            if (u < 640) {
                int col = u >> 2, q4 = u & 3;
                const __half* src = Wh + (size_t)col * G_DIM + koff + S * SK + q4 * 8;
                cp_async16(bs_base + (uint32_t)((buf * TN + col) * RPAD + q4 * 4) * 4u,
                           src);
            }
        }
    };
    auto load2 = [&](int S, int p0, float4* vi, float4* vj) {
        #pragma unroll
        for (int t = 0; t < 2; t++) {
            const size_t off = koff + S * SK + q * 4;
            vi[t] = *reinterpret_cast<const float4*>(
                G + (size_t)idx_i[p0 + t] * G_DIM + off);
            if (PAIR)
                vj[t] = *reinterpret_cast<const float4*>(
                    G + (size_t)idx_j[p0 + t] * G_DIM + off);
        }
    };
    auto prod_sts = [&](int p0, const float4* vi, const float4* vj, int buf) {
        #pragma unroll
        for (int t = 0; t < 2; t++) {
            __half2 h0, h1;
            if (PAIR) {
                h0 = __floats2half2_rn(vi[t].x * vj[t].x, vi[t].y * vj[t].y);
                h1 = __floats2half2_rn(vi[t].z * vj[t].z, vi[t].w * vj[t].w);
            } else {
                h0 = __floats2half2_rn(vi[t].x, vi[t].y);
                h1 = __floats2half2_rn(vi[t].z, vi[t].w);
            }
            const int row = rbase + 32 * (p0 + t);
            uint2 u;
            u.x = *reinterpret_cast<uint32_t*>(&h0);
            u.y = *reinterpret_cast<uint32_t*>(&h1);
            *reinterpret_cast<uint2*>(Au + (size_t)(buf * TM + row) * RPAD + q * 2) = u;
        }
    };
    auto mma_ks = [&](int buf, int ks) {
        uint32_t af[4][4];
        #pragma unroll
        for (int tm = 0; tm < 4; tm++) {
            uint32_t addr = a_lane_off
                + 4u * RPAD * (uint32_t)(buf * TM + warp_m * 64 + tm * 16)
                + 32u * (uint32_t)ks;
            ldmatrix_x4(af[tm], addr);
        }
        #pragma unroll
        for (int tn = 0; tn < 5; tn++) {
            uint32_t addr = b_lane_off
                + 4u * RPAD * (uint32_t)(buf * TN + warp_n * 40 + tn * 8)
                + 32u * (uint32_t)ks;
            uint32_t bf[2];
            ldmatrix_x2(bf, addr);
            #pragma unroll
            for (int tm = 0; tm < 4; tm++)
                mma_f16(acc[tm][tn], af[tm], bf);
        }
    };

    // ---- prologue: stage S=0 into buffer 0 ----
    {
        stage_B(0, 0);
        CP_COMMIT();
        float4 vi[2], vj[2];
        load2(0, 0, vi, vj);  prod_sts(0, vi, vj, 0);
        load2(0, 2, vi, vj);  prod_sts(2, vi, vj, 0);
        CP_WAIT0();
        __syncthreads();
    }

    for (int S = 0; S < nsup; S++) {
        const int cur = S & 1, nxt = cur ^ 1;
        const bool more = (S + 1 < nsup);
        if (more) stage_B(S + 1, nxt);
        CP_COMMIT();
        float4 vi[2], vj[2];
        if (more) load2(S + 1, 0, vi, vj);   // LDGs fly over MMA ks=0
        mma_ks(cur, 0);
        if (more) {
            prod_sts(0, vi, vj, nxt);
            load2(S + 1, 2, vi, vj);         // LDGs fly over MMA ks=1
        }
        mma_ks(cur, 1);
        if (more) prod_sts(2, vi, vj, nxt);
        CP_WAIT0();
        __syncthreads();                     // single barrier per stage
    }

    // ---- epilogue ----
    if (PAIR) {
        #pragma unroll
        for (int tm = 0; tm < 4; tm++) {
            #pragma unroll
            for (int rh = 0; rh < 2; rh++) {
                const int lr = warp_m * 64 + tm * 16 + rh * 8 + gID;
                const int p = base + lr;
                const int ii = m_ids[p], jj = a_ids[p], sp = spk_lbl[p];
                const float* Ar = d_Abuf + (size_t)ii * TN;
                const float* Br = d_Bbuf + (size_t)jj * TN;
                const float* bi = bias_s + sp * TN;
                float part = 0.f;
                #pragma unroll
                for (int tn = 0; tn < 5; tn++) {
                    const int h = warp_n * 40 + tn * 8 + tig * 2;
                    float2 av = *reinterpret_cast<const float2*>(Ar + h);
                    float2 bv = *reinterpret_cast<const float2*>(Br + h);
                    float v0 = acc[tm][tn][rh * 2 + 0] + av.x + bv.x + bi[h];
                    float v1 = acc[tm][tn][rh * 2 + 1] + av.y + bv.y + bi[h + 1];
                    part = fmaf(fmaxf(v0, 0.f), w2s[h], part);
                    part = fmaf(fmaxf(v1, 0.f), w2s[h + 1], part);
                }
                part += __shfl_xor_sync(0xffffffffu, part, 1);
                part += __shfl_xor_sync(0xffffffffu, part, 2);
                if (tig == 0) srow[warp_n][lr] = part;
            }
        }
        __syncthreads();
        if (tid < TM) {
            const int p = base + tid;
            d_scores[p] = srow[0][tid] + srow[1][tid] + srow[2][tid] + srow[3][tid]
                        + b2[0] + mscores[m_ids[p]] + mscores[a_ids[p]];
        }
    } else {
        float* out = &d_part[blockIdx.z][blockIdx.y][0];
        #pragma unroll
        for (int tm = 0; tm < 4; tm++) {
            #pragma unroll
            for (int rh = 0; rh < 2; rh++) {
                const int m = base + warp_m * 64 + tm * 16 + rh * 8 + gID;
                #pragma unroll
                for (int tn = 0; tn < 5; tn++) {
                    const int h = warp_n * 40 + tn * 8 + tig * 2;
                    float2 v = make_float2(acc[tm][tn][rh * 2 + 0],
                                           acc[tm][tn][rh * 2 + 1]);
                    *reinterpret_cast<float2*>(out + (size_t)m * TN + h) = v;
                }
            }
        }
    }
}

// ---------------------------------------------------------------------------
__global__ void combine_kernel() {
    const int TOT = 2 * N_MENT * TN / 4;   // float4 units per split
    int qk = blockIdx.x * 256 + threadIdx.x;
    if (qk >= TOT) return;
    const float4* p = reinterpret_cast<const float4*>(d_part);
    float4 a = p[qk], b = p[qk + TOT], c = p[qk + 2 * TOT], d = p[qk + 3 * TOT];
    float4 r;
    r.x = a.x + b.x + c.x + d.x;
    r.y = a.y + b.y + c.y + d.y;
    r.z = a.z + b.z + c.z + d.z;
    r.w = a.w + b.w + c.w + d.w;
    const int HALF = TOT / 2;
    if (qk < HALF) reinterpret_cast<float4*>(d_Abuf)[qk] = r;
    else           reinterpret_cast<float4*>(d_Bbuf)[qk - HALF] = r;
}

// ---------------------------------------------------------------------------
__global__ void softmax_kernel(const int* __restrict__ seg_ids,
                               float* __restrict__ out) {
    const int s = (blockIdx.x * blockDim.x + threadIdx.x) >> 5;
    const int lane = threadIdx.x & 31;
    if (s >= N_SEG) return;

    int lo = 0, hi = N_PAIRS;
    while (lo < hi) { int mid = (lo + hi) >> 1; if (seg_ids[mid] < s) lo = mid + 1; else hi = mid; }
    const int start = lo;
    hi = N_PAIRS;
    while (lo < hi) { int mid = (lo + hi) >> 1; if (seg_ids[mid] <= s) lo = mid + 1; else hi = mid; }
    const int end = lo;

    float m = 0.f;
    for (int p = start + lane; p < end; p += 32) m = fmaxf(m, d_scores[p]);
    #pragma unroll
    for (int o = 16; o; o >>= 1) m = fmaxf(m, __shfl_xor_sync(0xffffffffu, m, o));

    float sum = 0.f;
    for (int p = start + lane; p < end; p += 32) sum += expf(d_scores[p] - m);
    #pragma unroll
    for (int o = 16; o; o >>= 1) sum += __shfl_xor_sync(0xffffffffu, sum, o);

    const float eps_e = expf(-m);
    const float inv = 1.f / (sum + eps_e);
    for (int p = start + lane; p < end; p += 32)
        out[p] = expf(d_scores[p] - m) * inv;
    if (lane == 0) out[N_PAIRS + s] = eps_e * inv;
}

// ---------------------------------------------------------------------------
extern "C" void kernel_launch(void* const* d_in, const int* in_sizes, int n_in,
                              void* d_out, int out_size) {
    const float* g_i            = (const float*)d_in[0];
    const float* mention_scores = (const float*)d_in[1];
    const float* speaker_embed  = (const float*)d_in[2];
    const float* W1             = (const float*)d_in[3];
    const float* b1             = (const float*)d_in[4];
    const float* W2             = (const float*)d_in[5];
    const float* b2             = (const float*)d_in[6];
    const int*   mention_ids    = (const int*)d_in[7];
    const int*   antecedent_ids = (const int*)d_in[8];
    const int*   speaker_labels = (const int*)d_in[9];
    const int*   segment_ids    = (const int*)d_in[10];
    float* out = (float*)d_out;

    cudaFuncSetAttribute(mma_kernel<false>,
                         cudaFuncAttributeMaxDynamicSharedMemorySize, DYN_BYTES);
    cudaFuncSetAttribute(mma_kernel<true>,
                         cudaFuncAttributeMaxDynamicSharedMemorySize, DYN_BYTES);

    prep_w_kernel<<<dim3(G_DIM / 32, TN / 32, 3), dim3(32, 8)>>>(W1);
    bias_kernel<<<1, 256>>>(speaker_embed, W1, b1);
    // precompute: 32 M-tiles x 2 sections x 4 K-splits = 256 CTAs (full wave)
    mma_kernel<false><<<dim3(N_MENT / TM, 2, KSPLIT), 256, DYN_BYTES>>>(
        g_i, mention_ids, antecedent_ids, speaker_labels, mention_scores,
        W2, b2, NSUP_PRE);
    combine_kernel<<<(2 * N_MENT * TN / 4 + 255) / 256, 256>>>();
    // pair bilinear + fused epilogue: 256 CTAs
    mma_kernel<true><<<dim3(N_PAIRS / TM, 1, 1), 256, DYN_BYTES>>>(
        g_i, mention_ids, antecedent_ids, speaker_labels, mention_scores,
        W2, b2, NSUP);
    softmax_kernel<<<(N_SEG * 32 + 255) / 256, 256>>>(segment_ids, out);
}

// round 11
// speedup vs baseline: 2.3718x; 1.0603x over previous
#include <cuda_runtime.h>
#include <cuda_fp16.h>
#include <cstdint>
#include <math.h>

#define G_DIM   2304
#define HIDDEN  150
#define N_PAIRS 32768
#define N_MENT  4096
#define N_SEG   1024

#define TM 128
#define TN 160
#define SK 32                    // K per stage
#define NSUP (G_DIM / SK)        // 72
#define KSPLIT 4
#define NSUP_PRE (NSUP / KSPLIT) // 18

#define RPAD 20    // uint row stride: ldmatrix phases hit all 32 banks

#define AS_UINTS (2 * TM * RPAD)           // 5120
#define BS_UINTS (2 * TN * RPAD)           // 6400
#define DYN_BYTES ((AS_UINTS + BS_UINTS) * 4)   // 46080

// ---------------- device scratch (static; no allocation) -------------------
__device__ __half d_Gh[N_MENT * G_DIM];           // g_i in fp16
__device__ __half d_Wh[3 * TN * G_DIM];           // W1^T fp16 [sec][h][k]
__device__ float d_part[KSPLIT][2][N_MENT * TN];  // precompute partials
__device__ float d_Abuf[N_MENT * TN];
__device__ float d_Bbuf[N_MENT * TN];
__device__ float d_bias[3 * TN];
__device__ float d_scores[N_PAIRS];

__device__ __forceinline__ uint32_t smem_u32(const void* p) {
    uint32_t a;
    asm("{ .reg .u64 t; cvta.to.shared.u64 t, %1; cvt.u32.u64 %0, t; }"
        : "=r"(a) : "l"(p));
    return a;
}
__device__ __forceinline__ void cp_async16(uint32_t dst, const void* src) {
    asm volatile("cp.async.cg.shared.global [%0], [%1], 16;"
                 :: "r"(dst), "l"(src) : "memory");
}
#define CP_COMMIT() asm volatile("cp.async.commit_group;" ::: "memory")
#define CP_WAIT0()  asm volatile("cp.async.wait_group 0;" ::: "memory")

__device__ __forceinline__ void mma_f16(float* d, const uint32_t* a,
                                        const uint32_t* b) {
    asm volatile(
        "mma.sync.aligned.m16n8k16.row.col.f32.f16.f16.f32 "
        "{%0,%1,%2,%3}, {%4,%5,%6,%7}, {%8,%9}, {%0,%1,%2,%3};"
        : "+f"(d[0]), "+f"(d[1]), "+f"(d[2]), "+f"(d[3])
        : "r"(a[0]), "r"(a[1]), "r"(a[2]), "r"(a[3]), "r"(b[0]), "r"(b[1]));
}
__device__ __forceinline__ void ldmatrix_x4(uint32_t* r, uint32_t addr) {
    asm volatile("ldmatrix.sync.aligned.m8n8.x4.shared.b16 {%0,%1,%2,%3}, [%4];"
                 : "=r"(r[0]), "=r"(r[1]), "=r"(r[2]), "=r"(r[3]) : "r"(addr));
}
__device__ __forceinline__ void ldmatrix_x2(uint32_t* r, uint32_t addr) {
    asm volatile("ldmatrix.sync.aligned.m8n8.x2.shared.b16 {%0,%1}, [%2];"
                 : "=r"(r[0]), "=r"(r[1]) : "r"(addr));
}

// ---------------------------------------------------------------------------
// g_i -> fp16
// ---------------------------------------------------------------------------
__global__ void prep_g_kernel(const float* __restrict__ G) {
    int idx = blockIdx.x * 256 + threadIdx.x;     // float4 units
    if (idx >= N_MENT * G_DIM / 4) return;
    float4 v = reinterpret_cast<const float4*>(G)[idx];
    __half2 h0 = __floats2half2_rn(v.x, v.y);
    __half2 h1 = __floats2half2_rn(v.z, v.w);
    uint2 u;
    u.x = *reinterpret_cast<uint32_t*>(&h0);
    u.y = *reinterpret_cast<uint32_t*>(&h1);
    reinterpret_cast<uint2*>(d_Gh)[idx] = u;
}

// ---------------------------------------------------------------------------
// Transpose W1 sections to fp16 [sec][h][k]; rows h>=150 zeroed.
// ---------------------------------------------------------------------------
__global__ void prep_w_kernel(const float* __restrict__ W1) {
    __shared__ float t[32][33];
    const int k0 = blockIdx.x * 32, h0 = blockIdx.y * 32, sec = blockIdx.z;
    const int tx = threadIdx.x, ty = threadIdx.y;
    #pragma unroll
    for (int r = 0; r < 4; r++) {
        int ky = ty + r * 8, h = h0 + tx;
        t[ky][tx] = (h < HIDDEN)
            ? W1[(size_t)(sec * G_DIM + k0 + ky) * HIDDEN + h] : 0.f;
    }
    __syncthreads();
    #pragma unroll
    for (int r = 0; r < 4; r++) {
        int hy = ty + r * 8;
        d_Wh[(size_t)sec * TN * G_DIM + (size_t)(h0 + hy) * G_DIM + k0 + tx] =
            __float2half_rn(t[tx][hy]);
    }
}

// ---------------------------------------------------------------------------
__global__ void bias_kernel(const float* __restrict__ spk,
                            const float* __restrict__ W1,
                            const float* __restrict__ b1) {
    const float* Wd = W1 + (size_t)(3 * G_DIM) * HIDDEN;
    for (int idx = threadIdx.x; idx < 3 * TN; idx += blockDim.x) {
        int s = idx / TN, h = idx % TN;
        float v = 0.f;
        if (h < HIDDEN) {
            v = b1[h];
            #pragma unroll
            for (int t = 0; t < 20; t++)
                v = fmaf(spk[s * 20 + t], Wd[(size_t)t * HIDDEN + h], v);
        }
        d_bias[idx] = v;
    }
}

// ---------------------------------------------------------------------------
// fp16 mma.sync GEMM (m16n8k16) with ldmatrix fragment loads, fp16 g_i.
// SK=32 stages, A+B double-buffered in dynamic smem, ONE barrier per stage.
// 8 warps (2 M x 4 N), warp tile 64x40.
//   PAIR=false: A tile staged by pure cp.async (straight copy of fp16 rows)
//   PAIR=true : A = hmul2(g[i], g[j]) gathered via uint2 loads
// ---------------------------------------------------------------------------
template<bool PAIR>
__global__ __launch_bounds__(256, 2)
void mma_kernel(const int*   __restrict__ m_ids,
                const int*   __restrict__ a_ids,
                const int*   __restrict__ spk_lbl,
                const float* __restrict__ mscores,
                const float* __restrict__ W2,
                const float* __restrict__ b2,
                int nsup) {
    extern __shared__ uint32_t dynu[];
    uint32_t* Au = dynu;                 // [2][TM][RPAD]
    uint32_t* Bu = dynu + AS_UINTS;      // [2][TN][RPAD]
    __shared__ float srow[4][TM];
    __shared__ float bias_s[3 * TN];
    __shared__ float w2s[TN];

    const int tid = threadIdx.x;
    const int wid = tid >> 5, lane = tid & 31;
    const int gID = lane >> 2, tig = lane & 3;
    const int warp_m = wid & 1, warp_n = wid >> 1;
    const int base = blockIdx.x * TM;
    const int koff = PAIR ? 0 : blockIdx.z * NSUP_PRE * SK;

    if (PAIR) {
        if (tid < TN) w2s[tid] = (tid < HIDDEN) ? W2[tid] : 0.f;
        for (int i = tid; i < 3 * TN; i += 256) bias_s[i] = d_bias[i];
    }

    const __half* Wh = d_Wh + (size_t)(PAIR ? 2 : blockIdx.y) * TN * G_DIM;

    // PAIR A-gather roles: 8 threads/row, q = k-quad (4 halfs)
    const int rbase = tid >> 3;   // 0..31
    const int q = tid & 7;        // 0..7
    int idx_i[4], idx_j[4];
    if (PAIR) {
        #pragma unroll
        for (int p = 0; p < 4; p++) {
            const int r = base + rbase + 32 * p;
            idx_i[p] = m_ids[r];
            idx_j[p] = a_ids[r];
        }
    }

    float acc[4][5][4];
    #pragma unroll
    for (int a = 0; a < 4; a++)
        #pragma unroll
        for (int b = 0; b < 5; b++)
            #pragma unroll
            for (int c = 0; c < 4; c++) acc[a][b][c] = 0.f;

    const uint32_t au_base = smem_u32(Au);
    const uint32_t bs_base = smem_u32(Bu);

    // ldmatrix lane-address components (bytes)
    const int a_rowsel = (lane & 7) + ((lane >> 3) & 1) * 8;
    const int a_ksel   = (lane >> 4) & 1;
    const uint32_t a_lane_off = au_base
        + 4u * ((uint32_t)a_rowsel * RPAD + (uint32_t)a_ksel * 4);
    const int b_colsel = lane & 7;
    const int b_ksel   = (lane >> 3) & 1;
    const uint32_t b_lane_off = bs_base
        + 4u * ((uint32_t)b_colsel * RPAD + (uint32_t)b_ksel * 4);

    auto stage_B = [&](int S, int buf) {
        #pragma unroll
        for (int it = 0; it < 3; it++) {
            int u = tid + it * 256;
            if (u < 640) {
                int col = u >> 2, q4 = u & 3;
                const __half* src = Wh + (size_t)col * G_DIM + koff + S * SK + q4 * 8;
                cp_async16(bs_base + (uint32_t)((buf * TN + col) * RPAD + q4 * 4) * 4u,
                           src);
            }
        }
    };
    // PRE: A tile = straight cp.async copy of fp16 rows
    auto stage_A_pre = [&](int S, int buf) {
        #pragma unroll
        for (int it = 0; it < 2; it++) {
            int u = tid + it * 256;          // 0..511
            int row = u >> 2, q4 = u & 3;
            const __half* src = d_Gh + (size_t)(base + row) * G_DIM
                              + koff + S * SK + q4 * 8;
            cp_async16(au_base + (uint32_t)((buf * TM + row) * RPAD + q4 * 4) * 4u,
                       src);
        }
    };
    // PAIR: gather uint2 (4 halfs) per row x 4 rows
    auto load4 = [&](int S, uint2* vi, uint2* vj) {
        const size_t off = koff + S * SK + q * 4;
        #pragma unroll
        for (int p = 0; p < 4; p++) {
            vi[p] = *reinterpret_cast<const uint2*>(
                d_Gh + (size_t)idx_i[p] * G_DIM + off);
            vj[p] = *reinterpret_cast<const uint2*>(
                d_Gh + (size_t)idx_j[p] * G_DIM + off);
        }
    };
    auto prod_sts4 = [&](const uint2* vi, const uint2* vj, int buf) {
        #pragma unroll
        for (int p = 0; p < 4; p++) {
            __half2 a0 = *reinterpret_cast<const __half2*>(&vi[p].x);
            __half2 a1 = *reinterpret_cast<const __half2*>(&vi[p].y);
            __half2 b0 = *reinterpret_cast<const __half2*>(&vj[p].x);
            __half2 b1 = *reinterpret_cast<const __half2*>(&vj[p].y);
            __half2 p0 = __hmul2(a0, b0);
            __half2 p1 = __hmul2(a1, b1);
            uint2 u;
            u.x = *reinterpret_cast<uint32_t*>(&p0);
            u.y = *reinterpret_cast<uint32_t*>(&p1);
            const int row = rbase + 32 * p;
            *reinterpret_cast<uint2*>(Au + (size_t)(buf * TM + row) * RPAD + q * 2) = u;
        }
    };
    auto mma_ks = [&](int buf, int ks) {
        uint32_t af[4][4];
        #pragma unroll
        for (int tm = 0; tm < 4; tm++) {
            uint32_t addr = a_lane_off
                + 4u * RPAD * (uint32_t)(buf * TM + warp_m * 64 + tm * 16)
                + 32u * (uint32_t)ks;
            ldmatrix_x4(af[tm], addr);
        }
        #pragma unroll
        for (int tn = 0; tn < 5; tn++) {
            uint32_t addr = b_lane_off
                + 4u * RPAD * (uint32_t)(buf * TN + warp_n * 40 + tn * 8)
                + 32u * (uint32_t)ks;
            uint32_t bf[2];
            ldmatrix_x2(bf, addr);
            #pragma unroll
            for (int tm = 0; tm < 4; tm++)
                mma_f16(acc[tm][tn], af[tm], bf);
        }
    };

    // ---- prologue: stage S=0 into buffer 0 ----
    if (PAIR) {
        stage_B(0, 0);
        CP_COMMIT();
        uint2 vi[4], vj[4];
        load4(0, vi, vj);
        prod_sts4(vi, vj, 0);
        CP_WAIT0();
        __syncthreads();
    } else {
        stage_B(0, 0);
        stage_A_pre(0, 0);
        CP_COMMIT();
        CP_WAIT0();
        __syncthreads();
    }

    for (int S = 0; S < nsup; S++) {
        const int cur = S & 1, nxt = cur ^ 1;
        const bool more = (S + 1 < nsup);
        if (PAIR) {
            if (more) stage_B(S + 1, nxt);
            CP_COMMIT();
            uint2 vi[4], vj[4];
            if (more) load4(S + 1, vi, vj);  // LDGs fly over MMA ks=0
            mma_ks(cur, 0);
            if (more) prod_sts4(vi, vj, nxt);
            mma_ks(cur, 1);
        } else {
            if (more) { stage_B(S + 1, nxt); stage_A_pre(S + 1, nxt); }
            CP_COMMIT();
            mma_ks(cur, 0);
            mma_ks(cur, 1);
        }
        CP_WAIT0();
        __syncthreads();                     // single barrier per stage
    }

    // ---- epilogue ----
    if (PAIR) {
        #pragma unroll
        for (int tm = 0; tm < 4; tm++) {
            #pragma unroll
            for (int rh = 0; rh < 2; rh++) {
                const int lr = warp_m * 64 + tm * 16 + rh * 8 + gID;
                const int p = base + lr;
                const int ii = m_ids[p], jj = a_ids[p], sp = spk_lbl[p];
                const float* Ar = d_Abuf + (size_t)ii * TN;
                const float* Br = d_Bbuf + (size_t)jj * TN;
                const float* bi = bias_s + sp * TN;
                float part = 0.f;
                #pragma unroll
                for (int tn = 0; tn < 5; tn++) {
                    const int h = warp_n * 40 + tn * 8 + tig * 2;
                    float2 av = *reinterpret_cast<const float2*>(Ar + h);
                    float2 bv = *reinterpret_cast<const float2*>(Br + h);
                    float v0 = acc[tm][tn][rh * 2 + 0] + av.x + bv.x + bi[h];
                    float v1 = acc[tm][tn][rh * 2 + 1] + av.y + bv.y + bi[h + 1];
                    part = fmaf(fmaxf(v0, 0.f), w2s[h], part);
                    part = fmaf(fmaxf(v1, 0.f), w2s[h + 1], part);
                }
                part += __shfl_xor_sync(0xffffffffu, part, 1);
                part += __shfl_xor_sync(0xffffffffu, part, 2);
                if (tig == 0) srow[warp_n][lr] = part;
            }
        }
        __syncthreads();
        if (tid < TM) {
            const int p = base + tid;
            d_scores[p] = srow[0][tid] + srow[1][tid] + srow[2][tid] + srow[3][tid]
                        + b2[0] + mscores[m_ids[p]] + mscores[a_ids[p]];
        }
    } else {
        float* out = &d_part[blockIdx.z][blockIdx.y][0];
        #pragma unroll
        for (int tm = 0; tm < 4; tm++) {
            #pragma unroll
            for (int rh = 0; rh < 2; rh++) {
                const int m = base + warp_m * 64 + tm * 16 + rh * 8 + gID;
                #pragma unroll
                for (int tn = 0; tn < 5; tn++) {
                    const int h = warp_n * 40 + tn * 8 + tig * 2;
                    float2 v = make_float2(acc[tm][tn][rh * 2 + 0],
                                           acc[tm][tn][rh * 2 + 1]);
                    *reinterpret_cast<float2*>(out + (size_t)m * TN + h) = v;
                }
            }
        }
    }
}

// ---------------------------------------------------------------------------
__global__ void combine_kernel() {
    const int TOT = 2 * N_MENT * TN / 4;   // float4 units per split
    int qk = blockIdx.x * 256 + threadIdx.x;
    if (qk >= TOT) return;
    const float4* p = reinterpret_cast<const float4*>(d_part);
    float4 a = p[qk], b = p[qk + TOT], c = p[qk + 2 * TOT], d = p[qk + 3 * TOT];
    float4 r;
    r.x = a.x + b.x + c.x + d.x;
    r.y = a.y + b.y + c.y + d.y;
    r.z = a.z + b.z + c.z + d.z;
    r.w = a.w + b.w + c.w + d.w;
    const int HALF = TOT / 2;
    if (qk < HALF) reinterpret_cast<float4*>(d_Abuf)[qk] = r;
    else           reinterpret_cast<float4*>(d_Bbuf)[qk - HALF] = r;
}

// ---------------------------------------------------------------------------
__global__ void softmax_kernel(const int* __restrict__ seg_ids,
                               float* __restrict__ out) {
    const int s = (blockIdx.x * blockDim.x + threadIdx.x) >> 5;
    const int lane = threadIdx.x & 31;
    if (s >= N_SEG) return;

    int lo = 0, hi = N_PAIRS;
    while (lo < hi) { int mid = (lo + hi) >> 1; if (seg_ids[mid] < s) lo = mid + 1; else hi = mid; }
    const int start = lo;
    hi = N_PAIRS;
    while (lo < hi) { int mid = (lo + hi) >> 1; if (seg_ids[mid] <= s) lo = mid + 1; else hi = mid; }
    const int end = lo;

    float m = 0.f;
    for (int p = start + lane; p < end; p += 32) m = fmaxf(m, d_scores[p]);
    #pragma unroll
    for (int o = 16; o; o >>= 1) m = fmaxf(m, __shfl_xor_sync(0xffffffffu, m, o));

    float sum = 0.f;
    for (int p = start + lane; p < end; p += 32) sum += expf(d_scores[p] - m);
    #pragma unroll
    for (int o = 16; o; o >>= 1) sum += __shfl_xor_sync(0xffffffffu, sum, o);

    const float eps_e = expf(-m);
    const float inv = 1.f / (sum + eps_e);
    for (int p = start + lane; p < end; p += 32)
        out[p] = expf(d_scores[p] - m) * inv;
    if (lane == 0) out[N_PAIRS + s] = eps_e * inv;
}

// ---------------------------------------------------------------------------
extern "C" void kernel_launch(void* const* d_in, const int* in_sizes, int n_in,
                              void* d_out, int out_size) {
    const float* g_i            = (const float*)d_in[0];
    const float* mention_scores = (const float*)d_in[1];
    const float* speaker_embed  = (const float*)d_in[2];
    const float* W1             = (const float*)d_in[3];
    const float* b1             = (const float*)d_in[4];
    const float* W2             = (const float*)d_in[5];
    const float* b2             = (const float*)d_in[6];
    const int*   mention_ids    = (const int*)d_in[7];
    const int*   antecedent_ids = (const int*)d_in[8];
    const int*   speaker_labels = (const int*)d_in[9];
    const int*   segment_ids    = (const int*)d_in[10];
    float* out = (float*)d_out;

    cudaFuncSetAttribute(mma_kernel<false>,
                         cudaFuncAttributeMaxDynamicSharedMemorySize, DYN_BYTES);
    cudaFuncSetAttribute(mma_kernel<true>,
                         cudaFuncAttributeMaxDynamicSharedMemorySize, DYN_BYTES);

    prep_g_kernel<<<(N_MENT * G_DIM / 4 + 255) / 256, 256>>>(g_i);
    prep_w_kernel<<<dim3(G_DIM / 32, TN / 32, 3), dim3(32, 8)>>>(W1);
    bias_kernel<<<1, 256>>>(speaker_embed, W1, b1);
    // precompute: 32 M-tiles x 2 sections x 4 K-splits = 256 CTAs (full wave)
    mma_kernel<false><<<dim3(N_MENT / TM, 2, KSPLIT), 256, DYN_BYTES>>>(
        mention_ids, antecedent_ids, speaker_labels, mention_scores,
        W2, b2, NSUP_PRE);
    combine_kernel<<<(2 * N_MENT * TN / 4 + 255) / 256, 256>>>();
    // pair bilinear + fused epilogue: 256 CTAs
    mma_kernel<true><<<dim3(N_PAIRS / TM, 1, 1), 256, DYN_BYTES>>>(
        mention_ids, antecedent_ids, speaker_labels, mention_scores,
        W2, b2, NSUP);
    softmax_kernel<<<(N_SEG * 32 + 255) / 256, 256>>>(segment_ids, out);
}

// round 12
// speedup vs baseline: 2.5633x; 1.0807x over previous
#include <cuda_runtime.h>
#include <cuda_fp16.h>
#include <cstdint>
#include <math.h>

#define G_DIM   2304
#define HIDDEN  150
#define N_PAIRS 32768
#define N_MENT  4096
#define N_SEG   1024

#define TM 128
#define TN 160
#define SK 64                    // K per stage (one 128B fp16 line per A row)
#define NSUP (G_DIM / SK)        // 36
#define KSPLIT 4
#define NSUP_PRE (NSUP / KSPLIT) // 9

#define RPAD 36    // uint row stride (32 data + 4 pad): ldmatrix/STS conflict-free

#define AS_UINTS (2 * TM * RPAD)           // 9216
#define BS_UINTS (2 * TN * RPAD)           // 11520
#define DYN_BYTES ((AS_UINTS + BS_UINTS) * 4)   // 82944

// ---------------- device scratch (static; no allocation) -------------------
__device__ __half d_Gh[N_MENT * G_DIM];           // g_i in fp16
__device__ __half d_Wh[3 * TN * G_DIM];           // W1^T fp16 [sec][h][k]
__device__ float d_part[KSPLIT][2][N_MENT * TN];  // precompute partials
__device__ float d_Abuf[N_MENT * TN];
__device__ float d_Bbuf[N_MENT * TN];
__device__ float d_bias[3 * TN];
__device__ float d_scores[N_PAIRS];

__device__ __forceinline__ uint32_t smem_u32(const void* p) {
    uint32_t a;
    asm("{ .reg .u64 t; cvta.to.shared.u64 t, %1; cvt.u32.u64 %0, t; }"
        : "=r"(a) : "l"(p));
    return a;
}
__device__ __forceinline__ void cp_async16(uint32_t dst, const void* src) {
    asm volatile("cp.async.cg.shared.global [%0], [%1], 16;"
                 :: "r"(dst), "l"(src) : "memory");
}
#define CP_COMMIT() asm volatile("cp.async.commit_group;" ::: "memory")
#define CP_WAIT0()  asm volatile("cp.async.wait_group 0;" ::: "memory")

__device__ __forceinline__ void mma_f16(float* d, const uint32_t* a,
                                        const uint32_t* b) {
    asm volatile(
        "mma.sync.aligned.m16n8k16.row.col.f32.f16.f16.f32 "
        "{%0,%1,%2,%3}, {%4,%5,%6,%7}, {%8,%9}, {%0,%1,%2,%3};"
        : "+f"(d[0]), "+f"(d[1]), "+f"(d[2]), "+f"(d[3])
        : "r"(a[0]), "r"(a[1]), "r"(a[2]), "r"(a[3]), "r"(b[0]), "r"(b[1]));
}
__device__ __forceinline__ void ldmatrix_x4(uint32_t* r, uint32_t addr) {
    asm volatile("ldmatrix.sync.aligned.m8n8.x4.shared.b16 {%0,%1,%2,%3}, [%4];"
                 : "=r"(r[0]), "=r"(r[1]), "=r"(r[2]), "=r"(r[3]) : "r"(addr));
}
__device__ __forceinline__ void ldmatrix_x2(uint32_t* r, uint32_t addr) {
    asm volatile("ldmatrix.sync.aligned.m8n8.x2.shared.b16 {%0,%1}, [%2];"
                 : "=r"(r[0]), "=r"(r[1]) : "r"(addr));
}

// ---------------------------------------------------------------------------
__global__ void prep_g_kernel(const float* __restrict__ G) {
    int idx = blockIdx.x * 256 + threadIdx.x;     // float4 units
    if (idx >= N_MENT * G_DIM / 4) return;
    float4 v = reinterpret_cast<const float4*>(G)[idx];
    __half2 h0 = __floats2half2_rn(v.x, v.y);
    __half2 h1 = __floats2half2_rn(v.z, v.w);
    uint2 u;
    u.x = *reinterpret_cast<uint32_t*>(&h0);
    u.y = *reinterpret_cast<uint32_t*>(&h1);
    reinterpret_cast<uint2*>(d_Gh)[idx] = u;
}

// ---------------------------------------------------------------------------
__global__ void prep_w_kernel(const float* __restrict__ W1) {
    __shared__ float t[32][33];
    const int k0 = blockIdx.x * 32, h0 = blockIdx.y * 32, sec = blockIdx.z;
    const int tx = threadIdx.x, ty = threadIdx.y;
    #pragma unroll
    for (int r = 0; r < 4; r++) {
        int ky = ty + r * 8, h = h0 + tx;
        t[ky][tx] = (h < HIDDEN)
            ? W1[(size_t)(sec * G_DIM + k0 + ky) * HIDDEN + h] : 0.f;
    }
    __syncthreads();
    #pragma unroll
    for (int r = 0; r < 4; r++) {
        int hy = ty + r * 8;
        d_Wh[(size_t)sec * TN * G_DIM + (size_t)(h0 + hy) * G_DIM + k0 + tx] =
            __float2half_rn(t[tx][hy]);
    }
}

// ---------------------------------------------------------------------------
__global__ void bias_kernel(const float* __restrict__ spk,
                            const float* __restrict__ W1,
                            const float* __restrict__ b1) {
    const float* Wd = W1 + (size_t)(3 * G_DIM) * HIDDEN;
    for (int idx = threadIdx.x; idx < 3 * TN; idx += blockDim.x) {
        int s = idx / TN, h = idx % TN;
        float v = 0.f;
        if (h < HIDDEN) {
            v = b1[h];
            #pragma unroll
            for (int t = 0; t < 20; t++)
                v = fmaf(spk[s * 20 + t], Wd[(size_t)t * HIDDEN + h], v);
        }
        d_bias[idx] = v;
    }
}

// ---------------------------------------------------------------------------
// fp16 mma.sync GEMM (m16n8k16), ldmatrix frags, SK=64 stages (36 / 9),
// A+B double-buffered in dynamic smem, ONE barrier per stage.
// 8 warps (2 M x 4 N), warp tile 64x40; 4 k-groups of 16 per stage.
//   PAIR=false: A tile staged by pure cp.async; partial K-split GEMM
//   PAIR=true : A = hmul2(g[i], g[j]); one uint4 = one 128B line per row
// ---------------------------------------------------------------------------
template<bool PAIR>
__global__ __launch_bounds__(256, 2)
void mma_kernel(const int*   __restrict__ m_ids,
                const int*   __restrict__ a_ids,
                const int*   __restrict__ spk_lbl,
                const float* __restrict__ mscores,
                const float* __restrict__ W2,
                const float* __restrict__ b2,
                int nsup) {
    extern __shared__ uint32_t dynu[];
    uint32_t* Au = dynu;                 // [2][TM][RPAD]
    uint32_t* Bu = dynu + AS_UINTS;      // [2][TN][RPAD]
    __shared__ float srow[4][TM];
    __shared__ float bias_s[3 * TN];
    __shared__ float w2s[TN];

    const int tid = threadIdx.x;
    const int wid = tid >> 5, lane = tid & 31;
    const int gID = lane >> 2, tig = lane & 3;
    const int warp_m = wid & 1, warp_n = wid >> 1;
    const int base = blockIdx.x * TM;
    const int koff = PAIR ? 0 : blockIdx.z * NSUP_PRE * SK;

    if (PAIR) {
        if (tid < TN) w2s[tid] = (tid < HIDDEN) ? W2[tid] : 0.f;
        for (int i = tid; i < 3 * TN; i += 256) bias_s[i] = d_bias[i];
    }

    const __half* Wh = d_Wh + (size_t)(PAIR ? 2 : blockIdx.y) * TN * G_DIM;

    // PAIR A-gather: 8 threads/row, q = 16B slot (8 halfs); 4 row passes.
    const int rbase = tid >> 3;   // 0..31
    const int q = tid & 7;        // 0..7
    int idx_i[4], idx_j[4];
    if (PAIR) {
        #pragma unroll
        for (int p = 0; p < 4; p++) {
            const int r = base + rbase + 32 * p;
            idx_i[p] = m_ids[r];
            idx_j[p] = a_ids[r];
        }
    }

    float acc[4][5][4];
    #pragma unroll
    for (int a = 0; a < 4; a++)
        #pragma unroll
        for (int b = 0; b < 5; b++)
            #pragma unroll
            for (int c = 0; c < 4; c++) acc[a][b][c] = 0.f;

    const uint32_t au_base = smem_u32(Au);
    const uint32_t bs_base = smem_u32(Bu);

    // ldmatrix lane-address components (bytes)
    const int a_rowsel = (lane & 7) + ((lane >> 3) & 1) * 8;
    const int a_ksel   = (lane >> 4) & 1;
    const uint32_t a_lane_off = au_base
        + 4u * ((uint32_t)a_rowsel * RPAD + (uint32_t)a_ksel * 4);
    const int b_colsel = lane & 7;
    const int b_ksel   = (lane >> 3) & 1;
    const uint32_t b_lane_off = bs_base
        + 4u * ((uint32_t)b_colsel * RPAD + (uint32_t)b_ksel * 4);

    auto stage_B = [&](int S, int buf) {
        // 160 cols x 128B = 1280 x 16B units
        #pragma unroll
        for (int it = 0; it < 5; it++) {
            int u = tid + it * 256;
            int col = u >> 3, q4 = u & 7;
            const __half* src = Wh + (size_t)col * G_DIM + koff + S * SK + q4 * 8;
            cp_async16(bs_base + (uint32_t)((buf * TN + col) * RPAD + q4 * 4) * 4u,
                       src);
        }
    };
    auto stage_A_pre = [&](int S, int buf) {
        // 128 rows x 128B = 1024 x 16B units
        #pragma unroll
        for (int it = 0; it < 4; it++) {
            int u = tid + it * 256;
            int row = u >> 3, q4 = u & 7;
            const __half* src = d_Gh + (size_t)(base + row) * G_DIM
                              + koff + S * SK + q4 * 8;
            cp_async16(au_base + (uint32_t)((buf * TM + row) * RPAD + q4 * 4) * 4u,
                       src);
        }
    };
    // gather 2 rows (p0, p0+1), one uint4 (8 halfs) each
    auto load2 = [&](int S, int p0, uint4* vi, uint4* vj) {
        const size_t off = koff + S * SK + q * 8;
        #pragma unroll
        for (int t = 0; t < 2; t++) {
            vi[t] = *reinterpret_cast<const uint4*>(
                d_Gh + (size_t)idx_i[p0 + t] * G_DIM + off);
            vj[t] = *reinterpret_cast<const uint4*>(
                d_Gh + (size_t)idx_j[p0 + t] * G_DIM + off);
        }
    };
    auto prod_sts2 = [&](int p0, const uint4* vi, const uint4* vj, int buf) {
        #pragma unroll
        for (int t = 0; t < 2; t++) {
            __half2 a0 = *reinterpret_cast<const __half2*>(&vi[t].x);
            __half2 a1 = *reinterpret_cast<const __half2*>(&vi[t].y);
            __half2 a2 = *reinterpret_cast<const __half2*>(&vi[t].z);
            __half2 a3 = *reinterpret_cast<const __half2*>(&vi[t].w);
            __half2 b0 = *reinterpret_cast<const __half2*>(&vj[t].x);
            __half2 b1 = *reinterpret_cast<const __half2*>(&vj[t].y);
            __half2 b2v = *reinterpret_cast<const __half2*>(&vj[t].z);
            __half2 b3 = *reinterpret_cast<const __half2*>(&vj[t].w);
            __half2 p0h = __hmul2(a0, b0);
            __half2 p1h = __hmul2(a1, b1);
            __half2 p2h = __hmul2(a2, b2v);
            __half2 p3h = __hmul2(a3, b3);
            uint4 u;
            u.x = *reinterpret_cast<uint32_t*>(&p0h);
            u.y = *reinterpret_cast<uint32_t*>(&p1h);
            u.z = *reinterpret_cast<uint32_t*>(&p2h);
            u.w = *reinterpret_cast<uint32_t*>(&p3h);
            const int row = rbase + 32 * (p0 + t);
            *reinterpret_cast<uint4*>(Au + (size_t)(buf * TM + row) * RPAD + q * 4) = u;
        }
    };
    auto mma_ks = [&](int buf, int ks) {           // ks = 0..3 (k16 groups)
        uint32_t af[4][4];
        #pragma unroll
        for (int tm = 0; tm < 4; tm++) {
            uint32_t addr = a_lane_off
                + 4u * RPAD * (uint32_t)(buf * TM + warp_m * 64 + tm * 16)
                + 32u * (uint32_t)ks;
            ldmatrix_x4(af[tm], addr);
        }
        #pragma unroll
        for (int tn = 0; tn < 5; tn++) {
            uint32_t addr = b_lane_off
                + 4u * RPAD * (uint32_t)(buf * TN + warp_n * 40 + tn * 8)
                + 32u * (uint32_t)ks;
            uint32_t bf[2];
            ldmatrix_x2(bf, addr);
            #pragma unroll
            for (int tm = 0; tm < 4; tm++)
                mma_f16(acc[tm][tn], af[tm], bf);
        }
    };

    // ---- prologue: stage S=0 into buffer 0 ----
    if (PAIR) {
        stage_B(0, 0);
        CP_COMMIT();
        uint4 vi[2], vj[2];
        load2(0, 0, vi, vj);  prod_sts2(0, vi, vj, 0);
        load2(0, 2, vi, vj);  prod_sts2(2, vi, vj, 0);
        CP_WAIT0();
        __syncthreads();
    } else {
        stage_B(0, 0);
        stage_A_pre(0, 0);
        CP_COMMIT();
        CP_WAIT0();
        __syncthreads();
    }

    for (int S = 0; S < nsup; S++) {
        const int cur = S & 1, nxt = cur ^ 1;
        const bool more = (S + 1 < nsup);
        if (PAIR) {
            if (more) stage_B(S + 1, nxt);
            CP_COMMIT();
            uint4 vi[2], vj[2];
            if (more) load2(S + 1, 0, vi, vj);  // LDGs fly over MMA ks 0-1
            mma_ks(cur, 0);
            mma_ks(cur, 1);
            if (more) {
                prod_sts2(0, vi, vj, nxt);
                load2(S + 1, 2, vi, vj);        // LDGs fly over MMA ks 2-3
            }
            mma_ks(cur, 2);
            mma_ks(cur, 3);
            if (more) prod_sts2(2, vi, vj, nxt);
        } else {
            if (more) { stage_B(S + 1, nxt); stage_A_pre(S + 1, nxt); }
            CP_COMMIT();
            mma_ks(cur, 0);
            mma_ks(cur, 1);
            mma_ks(cur, 2);
            mma_ks(cur, 3);
        }
        CP_WAIT0();
        __syncthreads();                     // single barrier per stage
    }

    // ---- epilogue ----
    if (PAIR) {
        #pragma unroll
        for (int tm = 0; tm < 4; tm++) {
            #pragma unroll
            for (int rh = 0; rh < 2; rh++) {
                const int lr = warp_m * 64 + tm * 16 + rh * 8 + gID;
                const int p = base + lr;
                const int ii = m_ids[p], jj = a_ids[p], sp = spk_lbl[p];
                const float* Ar = d_Abuf + (size_t)ii * TN;
                const float* Br = d_Bbuf + (size_t)jj * TN;
                const float* bi = bias_s + sp * TN;
                float part = 0.f;
                #pragma unroll
                for (int tn = 0; tn < 5; tn++) {
                    const int h = warp_n * 40 + tn * 8 + tig * 2;
                    float2 av = *reinterpret_cast<const float2*>(Ar + h);
                    float2 bv = *reinterpret_cast<const float2*>(Br + h);
                    float v0 = acc[tm][tn][rh * 2 + 0] + av.x + bv.x + bi[h];
                    float v1 = acc[tm][tn][rh * 2 + 1] + av.y + bv.y + bi[h + 1];
                    part = fmaf(fmaxf(v0, 0.f), w2s[h], part);
                    part = fmaf(fmaxf(v1, 0.f), w2s[h + 1], part);
                }
                part += __shfl_xor_sync(0xffffffffu, part, 1);
                part += __shfl_xor_sync(0xffffffffu, part, 2);
                if (tig == 0) srow[warp_n][lr] = part;
            }
        }
        __syncthreads();
        if (tid < TM) {
            const int p = base + tid;
            d_scores[p] = srow[0][tid] + srow[1][tid] + srow[2][tid] + srow[3][tid]
                        + b2[0] + mscores[m_ids[p]] + mscores[a_ids[p]];
        }
    } else {
        float* out = &d_part[blockIdx.z][blockIdx.y][0];
        #pragma unroll
        for (int tm = 0; tm < 4; tm++) {
            #pragma unroll
            for (int rh = 0; rh < 2; rh++) {
                const int m = base + warp_m * 64 + tm * 16 + rh * 8 + gID;
                #pragma unroll
                for (int tn = 0; tn < 5; tn++) {
                    const int h = warp_n * 40 + tn * 8 + tig * 2;
                    float2 v = make_float2(acc[tm][tn][rh * 2 + 0],
                                           acc[tm][tn][rh * 2 + 1]);
                    *reinterpret_cast<float2*>(out + (size_t)m * TN + h) = v;
                }
            }
        }
    }
}

// ---------------------------------------------------------------------------
__global__ void combine_kernel() {
    const int TOT = 2 * N_MENT * TN / 4;   // float4 units per split
    int qk = blockIdx.x * 256 + threadIdx.x;
    if (qk >= TOT) return;
    const float4* p = reinterpret_cast<const float4*>(d_part);
    float4 a = p[qk], b = p[qk + TOT], c = p[qk + 2 * TOT], d = p[qk + 3 * TOT];
    float4 r;
    r.x = a.x + b.x + c.x + d.x;
    r.y = a.y + b.y + c.y + d.y;
    r.z = a.z + b.z + c.z + d.z;
    r.w = a.w + b.w + c.w + d.w;
    const int HALF = TOT / 2;
    if (qk < HALF) reinterpret_cast<float4*>(d_Abuf)[qk] = r;
    else           reinterpret_cast<float4*>(d_Bbuf)[qk - HALF] = r;
}

// ---------------------------------------------------------------------------
__global__ void softmax_kernel(const int* __restrict__ seg_ids,
                               float* __restrict__ out) {
    const int s = (blockIdx.x * blockDim.x + threadIdx.x) >> 5;
    const int lane = threadIdx.x & 31;
    if (s >= N_SEG) return;

    int lo = 0, hi = N_PAIRS;
    while (lo < hi) { int mid = (lo + hi) >> 1; if (seg_ids[mid] < s) lo = mid + 1; else hi = mid; }
    const int start = lo;
    hi = N_PAIRS;
    while (lo < hi) { int mid = (lo + hi) >> 1; if (seg_ids[mid] <= s) lo = mid + 1; else hi = mid; }
    const int end = lo;

    float m = 0.f;
    for (int p = start + lane; p < end; p += 32) m = fmaxf(m, d_scores[p]);
    #pragma unroll
    for (int o = 16; o; o >>= 1) m = fmaxf(m, __shfl_xor_sync(0xffffffffu, m, o));

    float sum = 0.f;
    for (int p = start + lane; p < end; p += 32) sum += expf(d_scores[p] - m);
    #pragma unroll
    for (int o = 16; o; o >>= 1) sum += __shfl_xor_sync(0xffffffffu, sum, o);

    const float eps_e = expf(-m);
    const float inv = 1.f / (sum + eps_e);
    for (int p = start + lane; p < end; p += 32)
        out[p] = expf(d_scores[p] - m) * inv;
    if (lane == 0) out[N_PAIRS + s] = eps_e * inv;
}

// ---------------------------------------------------------------------------
extern "C" void kernel_launch(void* const* d_in, const int* in_sizes, int n_in,
                              void* d_out, int out_size) {
    const float* g_i            = (const float*)d_in[0];
    const float* mention_scores = (const float*)d_in[1];
    const float* speaker_embed  = (const float*)d_in[2];
    const float* W1             = (const float*)d_in[3];
    const float* b1             = (const float*)d_in[4];
    const float* W2             = (const float*)d_in[5];
    const float* b2             = (const float*)d_in[6];
    const int*   mention_ids    = (const int*)d_in[7];
    const int*   antecedent_ids = (const int*)d_in[8];
    const int*   speaker_labels = (const int*)d_in[9];
    const int*   segment_ids    = (const int*)d_in[10];
    float* out = (float*)d_out;

    cudaFuncSetAttribute(mma_kernel<false>,
                         cudaFuncAttributeMaxDynamicSharedMemorySize, DYN_BYTES);
    cudaFuncSetAttribute(mma_kernel<true>,
                         cudaFuncAttributeMaxDynamicSharedMemorySize, DYN_BYTES);

    prep_g_kernel<<<(N_MENT * G_DIM / 4 + 255) / 256, 256>>>(g_i);
    prep_w_kernel<<<dim3(G_DIM / 32, TN / 32, 3), dim3(32, 8)>>>(W1);
    bias_kernel<<<1, 256>>>(speaker_embed, W1, b1);
    // precompute: 32 M-tiles x 2 sections x 4 K-splits = 256 CTAs (full wave)
    mma_kernel<false><<<dim3(N_MENT / TM, 2, KSPLIT), 256, DYN_BYTES>>>(
        mention_ids, antecedent_ids, speaker_labels, mention_scores,
        W2, b2, NSUP_PRE);
    combine_kernel<<<(2 * N_MENT * TN / 4 + 255) / 256, 256>>>();
    // pair bilinear + fused epilogue: 256 CTAs
    mma_kernel<true><<<dim3(N_PAIRS / TM, 1, 1), 256, DYN_BYTES>>>(
        mention_ids, antecedent_ids, speaker_labels, mention_scores,
        W2, b2, NSUP);
    softmax_kernel<<<(N_SEG * 32 + 255) / 256, 256>>>(segment_ids, out);
}